// round 1
// baseline (speedup 1.0000x reference)
#include <cuda_runtime.h>
#include <math.h>

// ---------------------------------------------------------------- constants
#define S_LEN 2048
#define H_DIM 2048
#define NHEAD 16
#define DQK   128
#define DV    64
#define KVR   256
#define NEXP  8
#define INTER 1408
#define NFC1  (NEXP*INTER)   // 11264

// ---------------------------------------------------------------- scratch
__device__ float g_sa  [S_LEN*H_DIM];
__device__ float g_q   [S_LEN*H_DIM];
__device__ float g_ckv [S_LEN*320];
__device__ float g_kvn [S_LEN*KVR];
__device__ float g_kv  [S_LEN*H_DIM];
__device__ float g_kpe [S_LEN*64];
__device__ float g_ctx [S_LEN*NHEAD*DV];
__device__ float g_x2  [S_LEN*H_DIM];
__device__ float g_mlp [S_LEN*H_DIM];
__device__ float g_pr  [S_LEN*NEXP];
__device__ float g_h   [S_LEN*NFC1];

// ---------------------------------------------------------------- rmsnorm
__global__ void rmsnorm_kernel(const float* __restrict__ x, const float* __restrict__ w,
                               float* __restrict__ y, int W, int xs, int ys)
{
    int s = blockIdx.x, tid = threadIdx.x;
    const float* xr = x + (size_t)s * xs;
    float ss = 0.f;
    for (int i = tid; i < W; i += 256) { float v = xr[i]; ss += v * v; }
    __shared__ float red[256];
    red[tid] = ss; __syncthreads();
    for (int o = 128; o > 0; o >>= 1) { if (tid < o) red[tid] += red[tid + o]; __syncthreads(); }
    float inv = rsqrtf(red[0] / (float)W + 1e-6f);
    float* yr = y + (size_t)s * ys;
    for (int i = tid; i < W; i += 256) yr[i] = w[i] * xr[i] * inv;
}

// ---------------------------------------------------------------- rope
__global__ void rope_kernel(const int* __restrict__ positions,
                            float* __restrict__ q,
                            const float* __restrict__ ckv,
                            float* __restrict__ kpe)
{
    int s = blockIdx.x;
    float p = (float)positions[s];
    for (int idx = threadIdx.x; idx < NHEAD * 32 + 32; idx += blockDim.x) {
        int j = idx & 31;
        float ang = p * powf(10000.0f, -(float)j * (1.0f / 32.0f));
        float c = cosf(ang), sn = sinf(ang);
        if (idx < NHEAD * 32) {
            int hh = idx >> 5;
            float* xp = q + (size_t)s * H_DIM + hh * DQK + 64;
            float x0 = xp[j], x1 = xp[j + 32];
            xp[j]      = x0 * c - x1 * sn;
            xp[j + 32] = x1 * c + x0 * sn;
        } else {
            const float* xp = ckv + (size_t)s * 320 + 256;
            float x0 = xp[j], x1 = xp[j + 32];
            kpe[(size_t)s * 64 + j]      = x0 * c - x1 * sn;
            kpe[(size_t)s * 64 + j + 32] = x1 * c + x0 * sn;
        }
    }
}

// ---------------------------------------------------------------- gate softmax
__global__ void gate_kernel(const float* __restrict__ x, const float* __restrict__ w,
                            float* __restrict__ probs)
{
    int s = blockIdx.x;
    int warp = threadIdx.x >> 5, lane = threadIdx.x & 31;
    const float* xr = x + (size_t)s * H_DIM;
    const float* wr = w + (size_t)warp * H_DIM;
    float acc = 0.f;
    for (int i = lane; i < H_DIM; i += 32) acc += xr[i] * wr[i];
    #pragma unroll
    for (int o = 16; o; o >>= 1) acc += __shfl_xor_sync(0xffffffffu, acc, o);
    __shared__ float lg[8];
    if (lane == 0) lg[warp] = acc;
    __syncthreads();
    if (threadIdx.x == 0) {
        float mx = lg[0];
        #pragma unroll
        for (int e = 1; e < 8; e++) mx = fmaxf(mx, lg[e]);
        float sum = 0.f, ev[8];
        #pragma unroll
        for (int e = 0; e < 8; e++) { ev[e] = __expf(lg[e] - mx); sum += ev[e]; }
        float inv = 1.f / sum;
        #pragma unroll
        for (int e = 0; e < 8; e++) probs[(size_t)s * 8 + e] = ev[e] * inv;
    }
}

// ---------------------------------------------------------------- SGEMM
// C[M,N] = A[M,K] @ B[N,K]^T   (+epilogue)
// EPI: 0 plain, 1 silu(v)*probs[row, col/INTER], 2 v + extra[row,col]
// MOEB: B element (n,k) = fc2_w[k/INTER][n][k%INTER]
template<int EPI, bool MOEB>
__global__ __launch_bounds__(256, 2) void sgemm_nt(
    const float* __restrict__ A, const float* __restrict__ B,
    float* __restrict__ C, int M, int N, int K,
    const float* __restrict__ extra)
{
    __shared__ float As[2][16][132];
    __shared__ float Bs[2][16][132];
    const int tid = threadIdx.x;
    const int m0 = blockIdx.y * 128, n0 = blockIdx.x * 128;
    const int r  = tid >> 2;
    const int c4 = (tid & 3) * 4;
    const int ty = tid >> 4, tx = tid & 15;

    const float* Apt = A + (size_t)(m0 + r) * K + c4;
    float4 fa0, fa1, fb0, fb1;
    const float4 z4 = make_float4(0.f, 0.f, 0.f, 0.f);

    auto fetch = [&](int k0) {
        fa0 = *(const float4*)(Apt + k0);
        fa1 = *(const float4*)(Apt + (size_t)64 * K + k0);
        if (MOEB) {
            int e  = k0 / INTER;
            int ii = k0 - e * INTER + c4;
            const float* Bp = B + (size_t)e * ((size_t)H_DIM * INTER)
                                + (size_t)(n0 + r) * INTER + ii;
            fb0 = *(const float4*)Bp;
            fb1 = *(const float4*)(Bp + (size_t)64 * INTER);
        } else {
            const float* Bp = B + (size_t)(n0 + r) * K + k0 + c4;
            fb0 = (n0 + r      < N) ? *(const float4*)Bp : z4;
            fb1 = (n0 + r + 64 < N) ? *(const float4*)(Bp + (size_t)64 * K) : z4;
        }
    };
    auto stage = [&](int buf) {
        As[buf][c4+0][r]    = fa0.x; As[buf][c4+1][r]    = fa0.y;
        As[buf][c4+2][r]    = fa0.z; As[buf][c4+3][r]    = fa0.w;
        As[buf][c4+0][r+64] = fa1.x; As[buf][c4+1][r+64] = fa1.y;
        As[buf][c4+2][r+64] = fa1.z; As[buf][c4+3][r+64] = fa1.w;
        Bs[buf][c4+0][r]    = fb0.x; Bs[buf][c4+1][r]    = fb0.y;
        Bs[buf][c4+2][r]    = fb0.z; Bs[buf][c4+3][r]    = fb0.w;
        Bs[buf][c4+0][r+64] = fb1.x; Bs[buf][c4+1][r+64] = fb1.y;
        Bs[buf][c4+2][r+64] = fb1.z; Bs[buf][c4+3][r+64] = fb1.w;
    };

    float acc[8][8];
    #pragma unroll
    for (int i = 0; i < 8; i++)
        #pragma unroll
        for (int j = 0; j < 8; j++) acc[i][j] = 0.f;

    fetch(0); stage(0); __syncthreads();
    const int kt = K >> 4;
    int cur = 0;
    for (int t = 0; t < kt; t++) {
        if (t + 1 < kt) fetch((t + 1) << 4);
        #pragma unroll
        for (int kk = 0; kk < 16; kk++) {
            float4 a0 = *(const float4*)&As[cur][kk][ty * 8];
            float4 a1 = *(const float4*)&As[cur][kk][ty * 8 + 4];
            float4 b0 = *(const float4*)&Bs[cur][kk][tx * 8];
            float4 b1 = *(const float4*)&Bs[cur][kk][tx * 8 + 4];
            float a[8] = {a0.x, a0.y, a0.z, a0.w, a1.x, a1.y, a1.z, a1.w};
            float b[8] = {b0.x, b0.y, b0.z, b0.w, b1.x, b1.y, b1.z, b1.w};
            #pragma unroll
            for (int i = 0; i < 8; i++)
                #pragma unroll
                for (int j = 0; j < 8; j++) acc[i][j] = fmaf(a[i], b[j], acc[i][j]);
        }
        if (t + 1 < kt) { stage(cur ^ 1); __syncthreads(); cur ^= 1; }
    }

    #pragma unroll
    for (int i = 0; i < 8; i++) {
        int row = m0 + ty * 8 + i;
        #pragma unroll
        for (int j = 0; j < 8; j++) {
            int col = n0 + tx * 8 + j;
            if (col < N) {
                float v = acc[i][j];
                if (EPI == 1) {
                    float sg = 1.f / (1.f + __expf(-v));
                    v = v * sg * extra[(size_t)row * 8 + (col / INTER)];
                } else if (EPI == 2) {
                    v += extra[(size_t)row * N + col];
                }
                C[(size_t)row * N + col] = v;
            }
        }
    }
}

// ---------------------------------------------------------------- attention
// Flash-style, fp32. Block handles (head, 64 q rows). 256 threads (16x16, 4x4).
#define ATTN_SMEM ((2 * 128 * 68 + 64 * 64 + 64 * 68) * 4)

__global__ __launch_bounds__(256) void attn_kernel(
    const float* __restrict__ q, const float* __restrict__ kv,
    const float* __restrict__ kpe, float* __restrict__ ctx)
{
    extern __shared__ float sm[];
    float (*Qt)[68] = reinterpret_cast<float(*)[68]>(sm);
    float (*Kt)[68] = reinterpret_cast<float(*)[68]>(sm + 128 * 68);
    float (*Vs)[64] = reinterpret_cast<float(*)[64]>(sm + 2 * 128 * 68);
    float (*Pt)[68] = reinterpret_cast<float(*)[68]>(sm + 2 * 128 * 68 + 64 * 64);

    const int h  = blockIdx.y;
    const int qi = (int)gridDim.x - 1 - (int)blockIdx.x;   // heavy tiles first
    const int q0 = qi * 64;
    const int tid = threadIdx.x;
    const int ty = tid >> 4, tx = tid & 15;

    for (int i = tid; i < 64 * 128; i += 256) {
        int r = i >> 7, d = i & 127;
        Qt[d][r] = q[(size_t)(q0 + r) * H_DIM + h * DQK + d];
    }

    float m_i[4], l_i[4], o[4][4];
    #pragma unroll
    for (int i = 0; i < 4; i++) {
        m_i[i] = -1e30f; l_i[i] = 0.f;
        #pragma unroll
        for (int j = 0; j < 4; j++) o[i][j] = 0.f;
    }
    const float SC = 0.08838834764831845f;  // 128^-0.5

    for (int kt = 0; kt <= qi; kt++) {
        const int k0 = kt * 64;
        __syncthreads();
        for (int i = tid; i < 64 * 128; i += 256) {
            int r = i >> 7, d = i & 127;
            Kt[d][r] = (d < 64) ? kv[(size_t)(k0 + r) * H_DIM + h * DQK + d]
                                : kpe[(size_t)(k0 + r) * 64 + (d - 64)];
        }
        for (int i = tid; i < 64 * 64; i += 256) {
            int r = i >> 6, c = i & 63;
            Vs[r][c] = kv[(size_t)(k0 + r) * H_DIM + h * DQK + 64 + c];
        }
        __syncthreads();

        float s4[4][4];
        #pragma unroll
        for (int i = 0; i < 4; i++)
            #pragma unroll
            for (int j = 0; j < 4; j++) s4[i][j] = 0.f;

        #pragma unroll 8
        for (int kk = 0; kk < 128; kk++) {
            float4 av = *(const float4*)&Qt[kk][ty * 4];
            float4 bv = *(const float4*)&Kt[kk][tx * 4];
            float a[4] = {av.x, av.y, av.z, av.w};
            float b[4] = {bv.x, bv.y, bv.z, bv.w};
            #pragma unroll
            for (int i = 0; i < 4; i++)
                #pragma unroll
                for (int j = 0; j < 4; j++) s4[i][j] = fmaf(a[i], b[j], s4[i][j]);
        }

        const bool diag = (kt == qi);
        #pragma unroll
        for (int i = 0; i < 4; i++) {
            float mx = -1e30f;
            #pragma unroll
            for (int j = 0; j < 4; j++) {
                float v = s4[i][j] * SC;
                if (diag && (tx * 4 + j) > (ty * 4 + i)) v = -1e30f;
                s4[i][j] = v;
                mx = fmaxf(mx, v);
            }
            #pragma unroll
            for (int off = 8; off; off >>= 1)
                mx = fmaxf(mx, __shfl_xor_sync(0xffffffffu, mx, off));
            float mnew = fmaxf(m_i[i], mx);
            float rs = 0.f;
            #pragma unroll
            for (int j = 0; j < 4; j++) {
                float pv = __expf(s4[i][j] - mnew);
                s4[i][j] = pv; rs += pv;
            }
            #pragma unroll
            for (int off = 8; off; off >>= 1)
                rs += __shfl_xor_sync(0xffffffffu, rs, off);
            float corr = __expf(m_i[i] - mnew);
            l_i[i] = l_i[i] * corr + rs;
            m_i[i] = mnew;
            #pragma unroll
            for (int j = 0; j < 4; j++) o[i][j] *= corr;
        }
        #pragma unroll
        for (int i = 0; i < 4; i++)
            #pragma unroll
            for (int j = 0; j < 4; j++) Pt[tx * 4 + j][ty * 4 + i] = s4[i][j];
        __syncthreads();

        #pragma unroll 8
        for (int kk = 0; kk < 64; kk++) {
            float4 av = *(const float4*)&Pt[kk][ty * 4];
            float4 bv = *(const float4*)&Vs[kk][tx * 4];
            float a[4] = {av.x, av.y, av.z, av.w};
            float b[4] = {bv.x, bv.y, bv.z, bv.w};
            #pragma unroll
            for (int i = 0; i < 4; i++)
                #pragma unroll
                for (int j = 0; j < 4; j++) o[i][j] = fmaf(a[i], b[j], o[i][j]);
        }
    }

    #pragma unroll
    for (int i = 0; i < 4; i++) {
        float inv = 1.f / l_i[i];
        float4 vv = make_float4(o[i][0] * inv, o[i][1] * inv, o[i][2] * inv, o[i][3] * inv);
        *(float4*)&ctx[(size_t)(q0 + ty * 4 + i) * (NHEAD * DV) + h * DV + tx * 4] = vv;
    }
}

// ---------------------------------------------------------------- launch
extern "C" void kernel_launch(void* const* d_in, const int* in_sizes, int n_in,
                              void* d_out, int out_size)
{
    const int*   positions = (const int*)  d_in[0];
    const float* hidden    = (const float*)d_in[1];
    const float* in_ln     = (const float*)d_in[2];
    const float* qw        = (const float*)d_in[3];
    const float* kva_w     = (const float*)d_in[4];
    const float* kvaln     = (const float*)d_in[5];
    const float* kvb_w     = (const float*)d_in[6];
    const float* ow        = (const float*)d_in[7];
    const float* postln    = (const float*)d_in[8];
    const float* gatew     = (const float*)d_in[9];
    const float* fc1w      = (const float*)d_in[10];
    const float* fc2w      = (const float*)d_in[11];
    float* out = (float*)d_out;

    float *sa, *qb, *ckv, *kvn, *kvv, *kpe, *ctx, *x2, *mlp, *pr, *hbuf;
    cudaGetSymbolAddress((void**)&sa,   g_sa);
    cudaGetSymbolAddress((void**)&qb,   g_q);
    cudaGetSymbolAddress((void**)&ckv,  g_ckv);
    cudaGetSymbolAddress((void**)&kvn,  g_kvn);
    cudaGetSymbolAddress((void**)&kvv,  g_kv);
    cudaGetSymbolAddress((void**)&kpe,  g_kpe);
    cudaGetSymbolAddress((void**)&ctx,  g_ctx);
    cudaGetSymbolAddress((void**)&x2,   g_x2);
    cudaGetSymbolAddress((void**)&mlp,  g_mlp);
    cudaGetSymbolAddress((void**)&pr,   g_pr);
    cudaGetSymbolAddress((void**)&hbuf, g_h);

    // 1. input RMSNorm
    rmsnorm_kernel<<<S_LEN, 256>>>(hidden, in_ln, sa, H_DIM, H_DIM, H_DIM);
    // 2. q projection  [2048,2048] = sa @ qw^T
    sgemm_nt<0, false><<<dim3(H_DIM / 128, S_LEN / 128), 256>>>(
        sa, qw, qb, S_LEN, H_DIM, H_DIM, nullptr);
    // 3. kv_a projection [2048,320]
    sgemm_nt<0, false><<<dim3((320 + 127) / 128, S_LEN / 128), 256>>>(
        sa, kva_w, ckv, S_LEN, 320, H_DIM, nullptr);
    // 4. kv RMSNorm (first 256 cols of ckv)
    rmsnorm_kernel<<<S_LEN, 256>>>(ckv, kvaln, kvn, KVR, 320, KVR);
    // 5. kv_b projection [2048,2048]
    sgemm_nt<0, false><<<dim3(H_DIM / 128, S_LEN / 128), 256>>>(
        kvn, kvb_w, kvv, S_LEN, H_DIM, KVR, nullptr);
    // 6. RoPE (q_pe in place, k_pe -> g_kpe)
    rope_kernel<<<S_LEN, 256>>>(positions, qb, ckv, kpe);
    // 7. causal flash attention
    cudaFuncSetAttribute(attn_kernel, cudaFuncAttributeMaxDynamicSharedMemorySize, ATTN_SMEM);
    attn_kernel<<<dim3(S_LEN / 64, NHEAD), 256, ATTN_SMEM>>>(qb, kvv, kpe, ctx);
    // 8. o projection + residual -> x2
    sgemm_nt<2, false><<<dim3(H_DIM / 128, S_LEN / 128), 256>>>(
        ctx, ow, x2, S_LEN, H_DIM, NHEAD * DV, hidden);
    // 9. post RMSNorm
    rmsnorm_kernel<<<S_LEN, 256>>>(x2, postln, mlp, H_DIM, H_DIM, H_DIM);
    // 10. gate softmax
    gate_kernel<<<S_LEN, 256>>>(mlp, gatew, pr);
    // 11. fc1 + SiLU * probs   [2048, 11264]
    sgemm_nt<1, false><<<dim3(NFC1 / 128, S_LEN / 128), 256>>>(
        mlp, fc1w, hbuf, S_LEN, NFC1, H_DIM, pr);
    // 12. fc2 (expert-block-diagonal B) + residual -> out
    sgemm_nt<2, true><<<dim3(H_DIM / 128, S_LEN / 128), 256>>>(
        hbuf, fc2w, out, S_LEN, H_DIM, NFC1, x2);
}

// round 3
// speedup vs baseline: 1.9006x; 1.9006x over previous
#include <cuda_runtime.h>
#include <cuda_bf16.h>
#include <math.h>
#include <stdint.h>

// ---------------------------------------------------------------- constants
#define S_LEN 2048
#define H_DIM 2048
#define NHEAD 16
#define DQK   128
#define DV    64
#define KVR   256
#define NEXP  8
#define INTER 1408
#define NFC1  (NEXP*INTER)   // 11264

// ---------------------------------------------------------------- scratch (fp32)
__device__ float g_sa  [S_LEN*H_DIM];
__device__ float g_q   [S_LEN*H_DIM];
__device__ float g_ckv [S_LEN*320];
__device__ float g_kvn [S_LEN*KVR];
__device__ float g_kv  [S_LEN*H_DIM];
__device__ float g_kpe [S_LEN*64];
__device__ float g_x2  [S_LEN*H_DIM];
__device__ float g_mlp [S_LEN*H_DIM];
__device__ float g_pr  [S_LEN*NEXP];

// ---------------------------------------------------------------- scratch (bf16 hi/lo)
__device__ __nv_bfloat16 g_sa_h [S_LEN*H_DIM],  g_sa_l [S_LEN*H_DIM];
__device__ __nv_bfloat16 g_kvn_h[S_LEN*KVR],    g_kvn_l[S_LEN*KVR];
__device__ __nv_bfloat16 g_mlp_h[S_LEN*H_DIM],  g_mlp_l[S_LEN*H_DIM];
__device__ __nv_bfloat16 g_ctx_h[S_LEN*NHEAD*DV], g_ctx_l[S_LEN*NHEAD*DV];
__device__ __nv_bfloat16 g_hb_h [(size_t)S_LEN*NFC1], g_hb_l [(size_t)S_LEN*NFC1];
__device__ __nv_bfloat16 g_qw_h [H_DIM*H_DIM],  g_qw_l [H_DIM*H_DIM];
__device__ __nv_bfloat16 g_kbw_h[H_DIM*KVR],    g_kbw_l[H_DIM*KVR];
__device__ __nv_bfloat16 g_ow_h [H_DIM*NHEAD*DV], g_ow_l[H_DIM*NHEAD*DV];
__device__ __nv_bfloat16 g_f1_h [(size_t)NFC1*H_DIM], g_f1_l [(size_t)NFC1*H_DIM];
__device__ __nv_bfloat16 g_f2_h [(size_t)H_DIM*NFC1], g_f2_l [(size_t)H_DIM*NFC1];

// ---------------------------------------------------------------- helpers
__device__ __forceinline__ uint32_t smem_u32(const void* p) {
    uint32_t a;
    asm("{ .reg .u64 t; cvta.to.shared.u64 t, %1; cvt.u32.u64 %0, t; }" : "=r"(a) : "l"(p));
    return a;
}
__device__ __forceinline__ void cp_async16(uint32_t dst, const void* src) {
    asm volatile("cp.async.cg.shared.global [%0], [%1], 16;" :: "r"(dst), "l"(src));
}
__device__ __forceinline__ void ldsm_x4(uint32_t* r, uint32_t addr) {
    asm volatile("ldmatrix.sync.aligned.m8n8.x4.shared.b16 {%0,%1,%2,%3}, [%4];"
                 : "=r"(r[0]), "=r"(r[1]), "=r"(r[2]), "=r"(r[3]) : "r"(addr));
}
__device__ __forceinline__ void mma_bf16(float* c, const uint32_t* a, const uint32_t* b) {
    asm volatile("mma.sync.aligned.m16n8k16.row.col.f32.bf16.bf16.f32 "
                 "{%0,%1,%2,%3}, {%4,%5,%6,%7}, {%8,%9}, {%0,%1,%2,%3};"
                 : "+f"(c[0]), "+f"(c[1]), "+f"(c[2]), "+f"(c[3])
                 : "r"(a[0]), "r"(a[1]), "r"(a[2]), "r"(a[3]), "r"(b[0]), "r"(b[1]));
}

// ---------------------------------------------------------------- fp32 -> bf16 hi/lo converts
__device__ __forceinline__ void split4(const float4 v, uint2& ph, uint2& pl) {
    float a[4] = {v.x, v.y, v.z, v.w};
    uint32_t hh[4], ll[4];
    #pragma unroll
    for (int j = 0; j < 4; j++) {
        __nv_bfloat16 h = __float2bfloat16(a[j]);
        __nv_bfloat16 l = __float2bfloat16(a[j] - __bfloat162float(h));
        hh[j] = (uint32_t)__bfloat16_as_ushort(h);
        ll[j] = (uint32_t)__bfloat16_as_ushort(l);
    }
    ph.x = hh[0] | (hh[1] << 16); ph.y = hh[2] | (hh[3] << 16);
    pl.x = ll[0] | (ll[1] << 16); pl.y = ll[2] | (ll[3] << 16);
}

__global__ void cvt_kernel(const float* __restrict__ x, __nv_bfloat16* __restrict__ h,
                           __nv_bfloat16* __restrict__ l, size_t n4) {
    for (size_t i = (size_t)blockIdx.x * blockDim.x + threadIdx.x; i < n4;
         i += (size_t)gridDim.x * blockDim.x) {
        uint2 ph, pl;
        split4(((const float4*)x)[i], ph, pl);
        ((uint2*)h)[i] = ph; ((uint2*)l)[i] = pl;
    }
}

// fc2_w[e][n][i] -> B[n][e*INTER+i]
__global__ void cvt_fc2_kernel(const float* __restrict__ w,
                               __nv_bfloat16* __restrict__ h, __nv_bfloat16* __restrict__ l) {
    const size_t I4 = INTER / 4;
    const size_t tot = (size_t)NEXP * H_DIM * I4;
    for (size_t i = (size_t)blockIdx.x * blockDim.x + threadIdx.x; i < tot;
         i += (size_t)gridDim.x * blockDim.x) {
        size_t e = i / (H_DIM * I4);
        size_t r = i - e * H_DIM * I4;
        size_t n = r / I4, i4 = r - n * I4;
        float4 v = ((const float4*)(w + (e * H_DIM + n) * INTER))[i4];
        uint2 ph, pl; split4(v, ph, pl);
        size_t o4 = (n * NFC1 + e * INTER) / 4 + i4;
        ((uint2*)h)[o4] = ph; ((uint2*)l)[o4] = pl;
    }
}

// ---------------------------------------------------------------- rmsnorm (+hi/lo)
__global__ void rmsnorm_kernel(const float* __restrict__ x, const float* __restrict__ w,
                               float* __restrict__ y,
                               __nv_bfloat16* __restrict__ yh, __nv_bfloat16* __restrict__ yl,
                               int W, int xs, int ys)
{
    int s = blockIdx.x, tid = threadIdx.x;
    const float* xr = x + (size_t)s * xs;
    float ss = 0.f;
    for (int i = tid; i < W; i += 256) { float v = xr[i]; ss += v * v; }
    __shared__ float red[256];
    red[tid] = ss; __syncthreads();
    for (int o = 128; o > 0; o >>= 1) { if (tid < o) red[tid] += red[tid + o]; __syncthreads(); }
    float inv = rsqrtf(red[0] / (float)W + 1e-6f);
    float* yr = y + (size_t)s * ys;
    for (int i = tid; i < W; i += 256) {
        float v = w[i] * xr[i] * inv;
        yr[i] = v;
        if (yh) {
            __nv_bfloat16 h = __float2bfloat16(v);
            yh[(size_t)s * ys + i] = h;
            yl[(size_t)s * ys + i] = __float2bfloat16(v - __bfloat162float(h));
        }
    }
}

// ---------------------------------------------------------------- rope
__global__ void rope_kernel(const int* __restrict__ positions,
                            float* __restrict__ q,
                            const float* __restrict__ ckv,
                            float* __restrict__ kpe)
{
    int s = blockIdx.x;
    float p = (float)positions[s];
    for (int idx = threadIdx.x; idx < NHEAD * 32 + 32; idx += blockDim.x) {
        int j = idx & 31;
        float ang = p * powf(10000.0f, -(float)j * (1.0f / 32.0f));
        float c = cosf(ang), sn = sinf(ang);
        if (idx < NHEAD * 32) {
            int hh = idx >> 5;
            float* xp = q + (size_t)s * H_DIM + hh * DQK + 64;
            float x0 = xp[j], x1 = xp[j + 32];
            xp[j]      = x0 * c - x1 * sn;
            xp[j + 32] = x1 * c + x0 * sn;
        } else {
            const float* xp = ckv + (size_t)s * 320 + 256;
            float x0 = xp[j], x1 = xp[j + 32];
            kpe[(size_t)s * 64 + j]      = x0 * c - x1 * sn;
            kpe[(size_t)s * 64 + j + 32] = x1 * c + x0 * sn;
        }
    }
}

// ---------------------------------------------------------------- gate softmax
__global__ void gate_kernel(const float* __restrict__ x, const float* __restrict__ w,
                            float* __restrict__ probs)
{
    int s = blockIdx.x;
    int warp = threadIdx.x >> 5, lane = threadIdx.x & 31;
    const float* xr = x + (size_t)s * H_DIM;
    const float* wr = w + (size_t)warp * H_DIM;
    float acc = 0.f;
    for (int i = lane; i < H_DIM; i += 32) acc += xr[i] * wr[i];
    #pragma unroll
    for (int o = 16; o; o >>= 1) acc += __shfl_xor_sync(0xffffffffu, acc, o);
    __shared__ float lg[8];
    if (lane == 0) lg[warp] = acc;
    __syncthreads();
    if (threadIdx.x == 0) {
        float mx = lg[0];
        #pragma unroll
        for (int e = 1; e < 8; e++) mx = fmaxf(mx, lg[e]);
        float sum = 0.f, ev[8];
        #pragma unroll
        for (int e = 0; e < 8; e++) { ev[e] = __expf(lg[e] - mx); sum += ev[e]; }
        float invs = 1.f / sum;
        #pragma unroll
        for (int e = 0; e < 8; e++) probs[(size_t)s * 8 + e] = ev[e] * invs;
    }
}

// ---------------------------------------------------------------- SIMT GEMM (kv_a only)
__global__ __launch_bounds__(256, 2) void sgemm_nt(
    const float* __restrict__ A, const float* __restrict__ B,
    float* __restrict__ C, int M, int N, int K)
{
    __shared__ float As[2][16][132];
    __shared__ float Bs[2][16][132];
    const int tid = threadIdx.x;
    const int m0 = blockIdx.y * 128, n0 = blockIdx.x * 128;
    const int r  = tid >> 2;
    const int c4 = (tid & 3) * 4;
    const int ty = tid >> 4, tx = tid & 15;

    const float* Apt = A + (size_t)(m0 + r) * K + c4;
    float4 fa0, fa1, fb0, fb1;
    const float4 z4 = make_float4(0.f, 0.f, 0.f, 0.f);

    auto fetch = [&](int k0) {
        fa0 = *(const float4*)(Apt + k0);
        fa1 = *(const float4*)(Apt + (size_t)64 * K + k0);
        const float* Bp = B + (size_t)(n0 + r) * K + k0 + c4;
        fb0 = (n0 + r      < N) ? *(const float4*)Bp : z4;
        fb1 = (n0 + r + 64 < N) ? *(const float4*)(Bp + (size_t)64 * K) : z4;
    };
    auto stage = [&](int buf) {
        As[buf][c4+0][r]    = fa0.x; As[buf][c4+1][r]    = fa0.y;
        As[buf][c4+2][r]    = fa0.z; As[buf][c4+3][r]    = fa0.w;
        As[buf][c4+0][r+64] = fa1.x; As[buf][c4+1][r+64] = fa1.y;
        As[buf][c4+2][r+64] = fa1.z; As[buf][c4+3][r+64] = fa1.w;
        Bs[buf][c4+0][r]    = fb0.x; Bs[buf][c4+1][r]    = fb0.y;
        Bs[buf][c4+2][r]    = fb0.z; Bs[buf][c4+3][r]    = fb0.w;
        Bs[buf][c4+0][r+64] = fb1.x; Bs[buf][c4+1][r+64] = fb1.y;
        Bs[buf][c4+2][r+64] = fb1.z; Bs[buf][c4+3][r+64] = fb1.w;
    };

    float acc[8][8];
    #pragma unroll
    for (int i = 0; i < 8; i++)
        #pragma unroll
        for (int j = 0; j < 8; j++) acc[i][j] = 0.f;

    fetch(0); stage(0); __syncthreads();
    const int kt = K >> 4;
    int cur = 0;
    for (int t = 0; t < kt; t++) {
        if (t + 1 < kt) fetch((t + 1) << 4);
        #pragma unroll
        for (int kk = 0; kk < 16; kk++) {
            float4 a0 = *(const float4*)&As[cur][kk][ty * 8];
            float4 a1 = *(const float4*)&As[cur][kk][ty * 8 + 4];
            float4 b0 = *(const float4*)&Bs[cur][kk][tx * 8];
            float4 b1 = *(const float4*)&Bs[cur][kk][tx * 8 + 4];
            float a[8] = {a0.x, a0.y, a0.z, a0.w, a1.x, a1.y, a1.z, a1.w};
            float b[8] = {b0.x, b0.y, b0.z, b0.w, b1.x, b1.y, b1.z, b1.w};
            #pragma unroll
            for (int i = 0; i < 8; i++)
                #pragma unroll
                for (int j = 0; j < 8; j++) acc[i][j] = fmaf(a[i], b[j], acc[i][j]);
        }
        if (t + 1 < kt) { stage(cur ^ 1); __syncthreads(); cur ^= 1; }
    }

    #pragma unroll
    for (int i = 0; i < 8; i++) {
        int row = m0 + ty * 8 + i;
        #pragma unroll
        for (int j = 0; j < 8; j++) {
            int col = n0 + tx * 8 + j;
            if (col < N) C[(size_t)row * N + col] = acc[i][j];
        }
    }
}

// ---------------------------------------------------------------- bf16 mma.sync GEMM
// C[M,N] = (Ah+Al)[M,K] @ (Bh+Bl)[N,K]^T via Ah*Bh + Ah*Bl + Al*Bh, fp32 reg accum.
// EPI: 0 plain fp32, 1 silu(v)*probs -> bf16 hi/lo, 2 v+extra -> fp32
// Tile: 128x128, BK=32 bf16, 4-stage cp.async. 256 threads, warp = 64x32.
// Smem per tile: 128 rows * 80B (40 bf16, padded for conflict-free ldmatrix).
#define HG_STAGES 4
#define HG_TILE_B  (128 * 80)          // 10240 B
#define HG_STAGE_B (4 * HG_TILE_B)     // 40960 B
#define HG_SMEM    (HG_STAGES * HG_STAGE_B)
#define OFF_AH 0
#define OFF_AL (1 * HG_TILE_B)
#define OFF_BH (2 * HG_TILE_B)
#define OFF_BL (3 * HG_TILE_B)

template<int EPI>
__global__ __launch_bounds__(256, 1) void hgemm(
    const __nv_bfloat16* __restrict__ Ah, const __nv_bfloat16* __restrict__ Al,
    const __nv_bfloat16* __restrict__ Bh, const __nv_bfloat16* __restrict__ Bl,
    int M, int N, int K,
    float* __restrict__ C, const float* __restrict__ extra,
    __nv_bfloat16* __restrict__ Ch, __nv_bfloat16* __restrict__ Cl)
{
    extern __shared__ char smem[];
    const uint32_t sb = smem_u32(smem);
    const int tid = threadIdx.x, wid = tid >> 5, lane = tid & 31;
    const int n0 = blockIdx.x * 128, m0 = blockIdx.y * 128;
    const int wm = (wid >> 2) * 64, wn = (wid & 3) * 32;

    // per-thread load coords: 2 iterations x (row, 16B-chunk)
    const int r0_ = tid >> 2,        c0_ = (tid & 3);
    const int r1_ = (tid + 256) >> 2, c1_ = c0_;   // second half: rows 64..127

    auto load_stage = [&](int t) {
        const uint32_t st = sb + (t % HG_STAGES) * HG_STAGE_B;
        const int k0 = t * 32;
        const size_t aoff0 = (size_t)(m0 + r0_) * K + k0 + c0_ * 8;
        const size_t aoff1 = (size_t)(m0 + r1_) * K + k0 + c1_ * 8;
        const size_t boff0 = (size_t)(n0 + r0_) * K + k0 + c0_ * 8;
        const size_t boff1 = (size_t)(n0 + r1_) * K + k0 + c1_ * 8;
        const uint32_t d0 = r0_ * 80 + c0_ * 16;
        const uint32_t d1 = r1_ * 80 + c1_ * 16;
        cp_async16(st + OFF_AH + d0, Ah + aoff0);
        cp_async16(st + OFF_AH + d1, Ah + aoff1);
        cp_async16(st + OFF_AL + d0, Al + aoff0);
        cp_async16(st + OFF_AL + d1, Al + aoff1);
        cp_async16(st + OFF_BH + d0, Bh + boff0);
        cp_async16(st + OFF_BH + d1, Bh + boff1);
        cp_async16(st + OFF_BL + d0, Bl + boff0);
        cp_async16(st + OFF_BL + d1, Bl + boff1);
    };

    float acc[4][4][4];
    #pragma unroll
    for (int i = 0; i < 4; i++)
        #pragma unroll
        for (int j = 0; j < 4; j++)
            #pragma unroll
            for (int k = 0; k < 4; k++) acc[i][j][k] = 0.f;

    const int KT = K >> 5;
    #pragma unroll
    for (int t = 0; t < HG_STAGES; t++) {
        if (t < KT) load_stage(t);
        asm volatile("cp.async.commit_group;");
    }

    // ldmatrix per-lane address components
    const uint32_t a_row = (lane & 15);            // + mt*16 + wm
    const uint32_t a_chk = (lane >> 4);            // + ks*2
    const uint32_t b_row = ((lane >> 4) & 1) * 8 + (lane & 7);  // + p*16 + wn
    const uint32_t b_chk = ((lane >> 3) & 1);      // + ks*2

    for (int t = 0; t < KT; t++) {
        asm volatile("cp.async.wait_group %0;" :: "n"(HG_STAGES - 1));
        __syncthreads();
        const uint32_t st = sb + (t % HG_STAGES) * HG_STAGE_B;

        #pragma unroll
        for (int ks = 0; ks < 2; ks++) {
            uint32_t a_h[4][4], a_l[4][4], b_h[4][2], b_l[4][2];
            #pragma unroll
            for (int mt = 0; mt < 4; mt++) {
                uint32_t addr = st + (wm + mt * 16 + a_row) * 80 + (ks * 2 + a_chk) * 16;
                ldsm_x4(a_h[mt], addr + OFF_AH);
                ldsm_x4(a_l[mt], addr + OFF_AL);
            }
            #pragma unroll
            for (int p = 0; p < 2; p++) {
                uint32_t addr = st + (wn + p * 16 + b_row) * 80 + (ks * 2 + b_chk) * 16;
                uint32_t rh[4], rl[4];
                ldsm_x4(rh, addr + OFF_BH);
                ldsm_x4(rl, addr + OFF_BL);
                b_h[2*p][0] = rh[0]; b_h[2*p][1] = rh[1];
                b_h[2*p+1][0] = rh[2]; b_h[2*p+1][1] = rh[3];
                b_l[2*p][0] = rl[0]; b_l[2*p][1] = rl[1];
                b_l[2*p+1][0] = rl[2]; b_l[2*p+1][1] = rl[3];
            }
            #pragma unroll
            for (int mt = 0; mt < 4; mt++)
                #pragma unroll
                for (int nt = 0; nt < 4; nt++) {
                    mma_bf16(acc[mt][nt], a_h[mt], b_h[nt]);
                    mma_bf16(acc[mt][nt], a_h[mt], b_l[nt]);
                    mma_bf16(acc[mt][nt], a_l[mt], b_h[nt]);
                }
        }
        __syncthreads();
        if (t + HG_STAGES < KT) load_stage(t + HG_STAGES);
        asm volatile("cp.async.commit_group;");
    }

    // ---------------- epilogue
    const int erow = m0 + wm + (lane >> 2);
    const int ecol = n0 + wn + (lane & 3) * 2;
    float pfac = 0.f;
    if (EPI == 1) pfac = 0.f;  // loaded per-row below

    #pragma unroll
    for (int mt = 0; mt < 4; mt++) {
        #pragma unroll
        for (int half = 0; half < 2; half++) {
            const int row = erow + mt * 16 + half * 8;
            float pf;
            if (EPI == 1) pf = extra[(size_t)row * NEXP + (n0 / INTER)];
            #pragma unroll
            for (int nt = 0; nt < 4; nt++) {
                const int col = ecol + nt * 8;
                float v0 = acc[mt][nt][half * 2 + 0];
                float v1 = acc[mt][nt][half * 2 + 1];
                if (EPI == 0) {
                    *(float2*)&C[(size_t)row * N + col] = make_float2(v0, v1);
                } else if (EPI == 2) {
                    const float2 e2 = *(const float2*)&extra[(size_t)row * N + col];
                    *(float2*)&C[(size_t)row * N + col] = make_float2(v0 + e2.x, v1 + e2.y);
                } else {
                    float s0 = v0 / (1.f + __expf(-v0)) * pf;
                    float s1 = v1 / (1.f + __expf(-v1)) * pf;
                    __nv_bfloat16 h0 = __float2bfloat16(s0);
                    __nv_bfloat16 h1 = __float2bfloat16(s1);
                    __nv_bfloat16 l0 = __float2bfloat16(s0 - __bfloat162float(h0));
                    __nv_bfloat16 l1 = __float2bfloat16(s1 - __bfloat162float(h1));
                    uint32_t ph = (uint32_t)__bfloat16_as_ushort(h0) |
                                  ((uint32_t)__bfloat16_as_ushort(h1) << 16);
                    uint32_t pl = (uint32_t)__bfloat16_as_ushort(l0) |
                                  ((uint32_t)__bfloat16_as_ushort(l1) << 16);
                    *(uint32_t*)&Ch[(size_t)row * N + col] = ph;
                    *(uint32_t*)&Cl[(size_t)row * N + col] = pl;
                }
            }
        }
    }
}

// ---------------------------------------------------------------- attention (SIMT flash)
#define ATTN_SMEM ((2 * 128 * 68 + 64 * 64 + 64 * 68) * 4)

__global__ __launch_bounds__(256) void attn_kernel(
    const float* __restrict__ q, const float* __restrict__ kv,
    const float* __restrict__ kpe,
    __nv_bfloat16* __restrict__ ctxh, __nv_bfloat16* __restrict__ ctxl)
{
    extern __shared__ float sm[];
    float (*Qt)[68] = reinterpret_cast<float(*)[68]>(sm);
    float (*Kt)[68] = reinterpret_cast<float(*)[68]>(sm + 128 * 68);
    float (*Vs)[64] = reinterpret_cast<float(*)[64]>(sm + 2 * 128 * 68);
    float (*Pt)[68] = reinterpret_cast<float(*)[68]>(sm + 2 * 128 * 68 + 64 * 64);

    const int h  = blockIdx.y;
    const int qi = (int)gridDim.x - 1 - (int)blockIdx.x;
    const int q0 = qi * 64;
    const int tid = threadIdx.x;
    const int ty = tid >> 4, tx = tid & 15;

    for (int i = tid; i < 64 * 128; i += 256) {
        int r = i >> 7, d = i & 127;
        Qt[d][r] = q[(size_t)(q0 + r) * H_DIM + h * DQK + d];
    }

    float m_i[4], l_i[4], o[4][4];
    #pragma unroll
    for (int i = 0; i < 4; i++) {
        m_i[i] = -1e30f; l_i[i] = 0.f;
        #pragma unroll
        for (int j = 0; j < 4; j++) o[i][j] = 0.f;
    }
    const float SC = 0.08838834764831845f;

    for (int kt = 0; kt <= qi; kt++) {
        const int k0 = kt * 64;
        __syncthreads();
        for (int i = tid; i < 64 * 128; i += 256) {
            int r = i >> 7, d = i & 127;
            Kt[d][r] = (d < 64) ? kv[(size_t)(k0 + r) * H_DIM + h * DQK + d]
                                : kpe[(size_t)(k0 + r) * 64 + (d - 64)];
        }
        for (int i = tid; i < 64 * 64; i += 256) {
            int r = i >> 6, c = i & 63;
            Vs[r][c] = kv[(size_t)(k0 + r) * H_DIM + h * DQK + 64 + c];
        }
        __syncthreads();

        float s4[4][4];
        #pragma unroll
        for (int i = 0; i < 4; i++)
            #pragma unroll
            for (int j = 0; j < 4; j++) s4[i][j] = 0.f;

        #pragma unroll 8
        for (int kk = 0; kk < 128; kk++) {
            float4 av = *(const float4*)&Qt[kk][ty * 4];
            float4 bv = *(const float4*)&Kt[kk][tx * 4];
            float a[4] = {av.x, av.y, av.z, av.w};
            float b[4] = {bv.x, bv.y, bv.z, bv.w};
            #pragma unroll
            for (int i = 0; i < 4; i++)
                #pragma unroll
                for (int j = 0; j < 4; j++) s4[i][j] = fmaf(a[i], b[j], s4[i][j]);
        }

        const bool diag = (kt == qi);
        #pragma unroll
        for (int i = 0; i < 4; i++) {
            float mx = -1e30f;
            #pragma unroll
            for (int j = 0; j < 4; j++) {
                float v = s4[i][j] * SC;
                if (diag && (tx * 4 + j) > (ty * 4 + i)) v = -1e30f;
                s4[i][j] = v;
                mx = fmaxf(mx, v);
            }
            #pragma unroll
            for (int off = 8; off; off >>= 1)
                mx = fmaxf(mx, __shfl_xor_sync(0xffffffffu, mx, off));
            float mnew = fmaxf(m_i[i], mx);
            float rs = 0.f;
            #pragma unroll
            for (int j = 0; j < 4; j++) {
                float pv = __expf(s4[i][j] - mnew);
                s4[i][j] = pv; rs += pv;
            }
            #pragma unroll
            for (int off = 8; off; off >>= 1)
                rs += __shfl_xor_sync(0xffffffffu, rs, off);
            float corr = __expf(m_i[i] - mnew);
            l_i[i] = l_i[i] * corr + rs;
            m_i[i] = mnew;
            #pragma unroll
            for (int j = 0; j < 4; j++) o[i][j] *= corr;
        }
        #pragma unroll
        for (int i = 0; i < 4; i++)
            #pragma unroll
            for (int j = 0; j < 4; j++) Pt[tx * 4 + j][ty * 4 + i] = s4[i][j];
        __syncthreads();

        #pragma unroll 8
        for (int kk = 0; kk < 64; kk++) {
            float4 av = *(const float4*)&Pt[kk][ty * 4];
            float4 bv = *(const float4*)&Vs[kk][tx * 4];
            float a[4] = {av.x, av.y, av.z, av.w};
            float b[4] = {bv.x, bv.y, bv.z, bv.w};
            #pragma unroll
            for (int i = 0; i < 4; i++)
                #pragma unroll
                for (int j = 0; j < 4; j++) o[i][j] = fmaf(a[i], b[j], o[i][j]);
        }
    }

    #pragma unroll
    for (int i = 0; i < 4; i++) {
        float inv = 1.f / l_i[i];
        uint32_t hh[4], ll[4];
        #pragma unroll
        for (int j = 0; j < 4; j++) {
            float v = o[i][j] * inv;
            __nv_bfloat16 hb = __float2bfloat16(v);
            hh[j] = (uint32_t)__bfloat16_as_ushort(hb);
            ll[j] = (uint32_t)__bfloat16_as_ushort(__float2bfloat16(v - __bfloat162float(hb)));
        }
        size_t off = (size_t)(q0 + ty * 4 + i) * (NHEAD * DV) + h * DV + tx * 4;
        *(uint2*)&ctxh[off] = make_uint2(hh[0] | (hh[1] << 16), hh[2] | (hh[3] << 16));
        *(uint2*)&ctxl[off] = make_uint2(ll[0] | (ll[1] << 16), ll[2] | (ll[3] << 16));
    }
}

// ---------------------------------------------------------------- launch
extern "C" void kernel_launch(void* const* d_in, const int* in_sizes, int n_in,
                              void* d_out, int out_size)
{
    const int*   positions = (const int*)  d_in[0];
    const float* hidden    = (const float*)d_in[1];
    const float* in_ln     = (const float*)d_in[2];
    const float* qw        = (const float*)d_in[3];
    const float* kva_w     = (const float*)d_in[4];
    const float* kvaln     = (const float*)d_in[5];
    const float* kvb_w     = (const float*)d_in[6];
    const float* ow        = (const float*)d_in[7];
    const float* postln    = (const float*)d_in[8];
    const float* gatew     = (const float*)d_in[9];
    const float* fc1w      = (const float*)d_in[10];
    const float* fc2w      = (const float*)d_in[11];
    float* out = (float*)d_out;

    float *sa, *qb, *ckv, *kvn, *kvv, *kpe, *x2, *mlp, *pr;
    cudaGetSymbolAddress((void**)&sa,  g_sa);
    cudaGetSymbolAddress((void**)&qb,  g_q);
    cudaGetSymbolAddress((void**)&ckv, g_ckv);
    cudaGetSymbolAddress((void**)&kvn, g_kvn);
    cudaGetSymbolAddress((void**)&kvv, g_kv);
    cudaGetSymbolAddress((void**)&kpe, g_kpe);
    cudaGetSymbolAddress((void**)&x2,  g_x2);
    cudaGetSymbolAddress((void**)&mlp, g_mlp);
    cudaGetSymbolAddress((void**)&pr,  g_pr);

    __nv_bfloat16 *sah,*sal,*kvnh,*kvnl,*mlph,*mlpl,*ctxh,*ctxl,*hbh,*hbl;
    __nv_bfloat16 *qwh,*qwl,*kbwh,*kbwl,*owh,*owl,*f1h,*f1l,*f2h,*f2l;
    cudaGetSymbolAddress((void**)&sah,  g_sa_h);  cudaGetSymbolAddress((void**)&sal,  g_sa_l);
    cudaGetSymbolAddress((void**)&kvnh, g_kvn_h); cudaGetSymbolAddress((void**)&kvnl, g_kvn_l);
    cudaGetSymbolAddress((void**)&mlph, g_mlp_h); cudaGetSymbolAddress((void**)&mlpl, g_mlp_l);
    cudaGetSymbolAddress((void**)&ctxh, g_ctx_h); cudaGetSymbolAddress((void**)&ctxl, g_ctx_l);
    cudaGetSymbolAddress((void**)&hbh,  g_hb_h);  cudaGetSymbolAddress((void**)&hbl,  g_hb_l);
    cudaGetSymbolAddress((void**)&qwh,  g_qw_h);  cudaGetSymbolAddress((void**)&qwl,  g_qw_l);
    cudaGetSymbolAddress((void**)&kbwh, g_kbw_h); cudaGetSymbolAddress((void**)&kbwl, g_kbw_l);
    cudaGetSymbolAddress((void**)&owh,  g_ow_h);  cudaGetSymbolAddress((void**)&owl,  g_ow_l);
    cudaGetSymbolAddress((void**)&f1h,  g_f1_h);  cudaGetSymbolAddress((void**)&f1l,  g_f1_l);
    cudaGetSymbolAddress((void**)&f2h,  g_f2_h);  cudaGetSymbolAddress((void**)&f2l,  g_f2_l);

    cudaFuncSetAttribute(hgemm<0>, cudaFuncAttributeMaxDynamicSharedMemorySize, HG_SMEM);
    cudaFuncSetAttribute(hgemm<1>, cudaFuncAttributeMaxDynamicSharedMemorySize, HG_SMEM);
    cudaFuncSetAttribute(hgemm<2>, cudaFuncAttributeMaxDynamicSharedMemorySize, HG_SMEM);
    cudaFuncSetAttribute(attn_kernel, cudaFuncAttributeMaxDynamicSharedMemorySize, ATTN_SMEM);

    // weight converts
    cvt_kernel<<<4096, 256>>>(qw,    qwh,  qwl,  (size_t)H_DIM * H_DIM / 4);
    cvt_kernel<<<1024, 256>>>(kvb_w, kbwh, kbwl, (size_t)H_DIM * KVR / 4);
    cvt_kernel<<<2048, 256>>>(ow,    owh,  owl,  (size_t)H_DIM * NHEAD * DV / 4);
    cvt_kernel<<<8192, 256>>>(fc1w,  f1h,  f1l,  (size_t)NFC1 * H_DIM / 4);
    cvt_fc2_kernel<<<8192, 256>>>(fc2w, f2h, f2l);

    // 1. input RMSNorm (+hi/lo)
    rmsnorm_kernel<<<S_LEN, 256>>>(hidden, in_ln, sa, sah, sal, H_DIM, H_DIM, H_DIM);
    // 2. q projection (tensor)
    hgemm<0><<<dim3(16, 16), 256, HG_SMEM>>>(sah, sal, qwh, qwl,
        S_LEN, H_DIM, H_DIM, qb, nullptr, nullptr, nullptr);
    // 3. kv_a projection (SIMT, N=320)
    sgemm_nt<<<dim3(3, 16), 256>>>(sa, kva_w, ckv, S_LEN, 320, H_DIM);
    // 4. kv RMSNorm (+hi/lo)
    rmsnorm_kernel<<<S_LEN, 256>>>(ckv, kvaln, kvn, kvnh, kvnl, KVR, 320, KVR);
    // 5. kv_b projection (tensor)
    hgemm<0><<<dim3(16, 16), 256, HG_SMEM>>>(kvnh, kvnl, kbwh, kbwl,
        S_LEN, H_DIM, KVR, kvv, nullptr, nullptr, nullptr);
    // 6. RoPE
    rope_kernel<<<S_LEN, 256>>>(positions, qb, ckv, kpe);
    // 7. attention (writes ctx hi/lo)
    attn_kernel<<<dim3(S_LEN / 64, NHEAD), 256, ATTN_SMEM>>>(qb, kvv, kpe, ctxh, ctxl);
    // 8. o projection + residual (tensor)
    hgemm<2><<<dim3(16, 16), 256, HG_SMEM>>>(ctxh, ctxl, owh, owl,
        S_LEN, H_DIM, NHEAD * DV, x2, hidden, nullptr, nullptr);
    // 9. post RMSNorm (+hi/lo)
    rmsnorm_kernel<<<S_LEN, 256>>>(x2, postln, mlp, mlph, mlpl, H_DIM, H_DIM, H_DIM);
    // 10. gate softmax
    gate_kernel<<<S_LEN, 256>>>(mlp, gatew, pr);
    // 11. fc1 + SiLU*probs -> hbuf hi/lo (tensor)
    hgemm<1><<<dim3(NFC1 / 128, 16), 256, HG_SMEM>>>(mlph, mlpl, f1h, f1l,
        S_LEN, NFC1, H_DIM, nullptr, pr, hbh, hbl);
    // 12. fc2 + residual -> out (tensor)
    hgemm<2><<<dim3(16, 16), 256, HG_SMEM>>>(hbh, hbl, f2h, f2l,
        S_LEN, H_DIM, NFC1, out, x2, nullptr, nullptr);
}

// round 4
// speedup vs baseline: 2.4823x; 1.3061x over previous
#include <cuda_runtime.h>
#include <cuda_bf16.h>
#include <math.h>
#include <stdint.h>

// ---------------------------------------------------------------- constants
#define S_LEN 2048
#define H_DIM 2048
#define NHEAD 16
#define DQK   128
#define DV    64
#define KVR   256
#define NEXP  8
#define INTER 1408
#define NFC1  (NEXP*INTER)   // 11264

// blocked layout: 16KB block = 128 rows x 64 cols bf16, SW128-swizzled
// KB(x) = K/64 blocks per row-of-blocks
#define KB_H    (H_DIM/64)   // 32
#define KB_KVR  (KVR/64)     // 4
#define KB_CTX  ((NHEAD*DV)/64) // 16
#define KB_FC1  (H_DIM/64)   // 32
#define KB_FC2  (NFC1/64)    // 176

// ---------------------------------------------------------------- scratch (fp32)
__device__ float g_sa  [S_LEN*H_DIM];
__device__ float g_q   [S_LEN*H_DIM];
__device__ float g_ckv [S_LEN*320];
__device__ float g_kvn [S_LEN*KVR];
__device__ float g_kv  [S_LEN*H_DIM];
__device__ float g_kpe [S_LEN*64];
__device__ float g_x2  [S_LEN*H_DIM];
__device__ float g_mlp [S_LEN*H_DIM];
__device__ float g_pr  [S_LEN*NEXP];

// ---------------------------------------------------------------- scratch (blocked bf16 hi/lo)
__device__ __nv_bfloat16 g_sa_h [S_LEN*H_DIM],   g_sa_l [S_LEN*H_DIM];
__device__ __nv_bfloat16 g_kvn_h[S_LEN*KVR],     g_kvn_l[S_LEN*KVR];
__device__ __nv_bfloat16 g_mlp_h[S_LEN*H_DIM],   g_mlp_l[S_LEN*H_DIM];
__device__ __nv_bfloat16 g_ctx_h[S_LEN*NHEAD*DV],g_ctx_l[S_LEN*NHEAD*DV];
__device__ __nv_bfloat16 g_hb_h [(size_t)S_LEN*NFC1], g_hb_l [(size_t)S_LEN*NFC1];
__device__ __nv_bfloat16 g_qw_h [H_DIM*H_DIM],   g_qw_l [H_DIM*H_DIM];
__device__ __nv_bfloat16 g_kbw_h[H_DIM*KVR],     g_kbw_l[H_DIM*KVR];
__device__ __nv_bfloat16 g_ow_h [H_DIM*NHEAD*DV],g_ow_l [H_DIM*NHEAD*DV];
__device__ __nv_bfloat16 g_f1_h [(size_t)NFC1*H_DIM], g_f1_l [(size_t)NFC1*H_DIM];
__device__ __nv_bfloat16 g_f2_h [(size_t)H_DIM*NFC1], g_f2_l [(size_t)H_DIM*NFC1];

// ---------------------------------------------------------------- helpers
__device__ __forceinline__ uint32_t smem_u32(const void* p) {
    uint32_t a;
    asm("{ .reg .u64 t; cvta.to.shared.u64 t, %1; cvt.u32.u64 %0, t; }" : "=r"(a) : "l"(p));
    return a;
}
#define SWZ(off) ((off) ^ (((off) >> 3) & 0x70u))

__device__ __forceinline__ void ldsm_x4(uint32_t* r, uint32_t addr) {
    asm volatile("ldmatrix.sync.aligned.m8n8.x4.shared.b16 {%0,%1,%2,%3}, [%4];"
                 : "=r"(r[0]), "=r"(r[1]), "=r"(r[2]), "=r"(r[3]) : "r"(addr));
}
__device__ __forceinline__ void mma_bf16(float* c, const uint32_t* a, const uint32_t* b) {
    asm volatile("mma.sync.aligned.m16n8k16.row.col.f32.bf16.bf16.f32 "
                 "{%0,%1,%2,%3}, {%4,%5,%6,%7}, {%8,%9}, {%0,%1,%2,%3};"
                 : "+f"(c[0]), "+f"(c[1]), "+f"(c[2]), "+f"(c[3])
                 : "r"(a[0]), "r"(a[1]), "r"(a[2]), "r"(a[3]), "r"(b[0]), "r"(b[1]));
}
#define MBAR_INIT(a, c) asm volatile("mbarrier.init.shared.b64 [%0], %1;" :: "r"(a), "r"(c) : "memory")
#define MBAR_EXPECT(a, b) asm volatile("mbarrier.arrive.expect_tx.shared.b64 _, [%0], %1;" :: "r"(a), "r"(b) : "memory")
#define MBAR_WAIT(a, ph) do { \
    asm volatile("{\n\t.reg .pred P1;\n\tWL_%=:\n\t" \
        "mbarrier.try_wait.parity.acquire.cta.shared::cta.b64 P1, [%0], %1, 0x989680;\n\t" \
        "@P1 bra.uni WD_%=;\n\tbra.uni WL_%=;\n\tWD_%=:\n\t}" \
        :: "r"(a), "r"(ph) : "memory"); } while (0)
__device__ __forceinline__ void bulk_g2s(uint32_t dst, const void* src, uint32_t bytes, uint32_t mbar) {
    asm volatile("cp.async.bulk.shared::cluster.global.mbarrier::complete_tx::bytes [%0], [%1], %2, [%3];"
                 :: "r"(dst), "l"(src), "r"(bytes), "r"(mbar) : "memory");
}

// pack 8 fp32 -> hi uint4 + lo uint4 (bf16 split)
__device__ __forceinline__ void split8(const float* v, uint4& ph, uint4& pl) {
    uint32_t hh[8], ll[8];
    #pragma unroll
    for (int j = 0; j < 8; j++) {
        __nv_bfloat16 h = __float2bfloat16(v[j]);
        __nv_bfloat16 l = __float2bfloat16(v[j] - __bfloat162float(h));
        hh[j] = (uint32_t)__bfloat16_as_ushort(h);
        ll[j] = (uint32_t)__bfloat16_as_ushort(l);
    }
    ph = make_uint4(hh[0]|(hh[1]<<16), hh[2]|(hh[3]<<16), hh[4]|(hh[5]<<16), hh[6]|(hh[7]<<16));
    pl = make_uint4(ll[0]|(ll[1]<<16), ll[2]|(ll[3]<<16), ll[4]|(ll[5]<<16), ll[6]|(ll[7]<<16));
}
// blocked chunk byte offset: block (rb, cb-chunk base), row r in [0,128), chunk c8 in [0,8)
__device__ __forceinline__ size_t blk_chunk_off(int blk_idx, int row, int c8) {
    uint32_t inner = (uint32_t)row * 128u + (uint32_t)c8 * 16u;
    return ((size_t)blk_idx << 14) + SWZ(inner);
}

// ---------------------------------------------------------------- weight converts (blocked)
// src: W[N][K] fp32 row-major -> blocked hi/lo
__global__ void cvt_blk_kernel(const float* __restrict__ src,
                               __nv_bfloat16* __restrict__ H, __nv_bfloat16* __restrict__ L,
                               int N, int K) {
    const int KC = K >> 3;              // 8-col chunks
    const int KBk = K >> 6;
    const size_t tot = (size_t)N * KC;
    for (size_t idx = (size_t)blockIdx.x * blockDim.x + threadIdx.x; idx < tot;
         idx += (size_t)gridDim.x * blockDim.x) {
        int n = (int)(idx / KC), c = (int)(idx - (size_t)n * KC);
        float v[8];
        const float4 f0 = *(const float4*)(src + (size_t)n * K + c * 8);
        const float4 f1 = *(const float4*)(src + (size_t)n * K + c * 8 + 4);
        v[0]=f0.x; v[1]=f0.y; v[2]=f0.z; v[3]=f0.w; v[4]=f1.x; v[5]=f1.y; v[6]=f1.z; v[7]=f1.w;
        uint4 ph, pl; split8(v, ph, pl);
        size_t off = blk_chunk_off((n >> 7) * KBk + (c >> 3), n & 127, c & 7);
        *(uint4*)((char*)H + off) = ph;
        *(uint4*)((char*)L + off) = pl;
    }
}

// fc2: logical B[n][k], k = e*INTER+i, element = w[e][n][i] -> blocked
__global__ void cvt_fc2_blk_kernel(const float* __restrict__ w,
                                   __nv_bfloat16* __restrict__ H, __nv_bfloat16* __restrict__ L) {
    const int KC = NFC1 >> 3;  // 1408
    const size_t tot = (size_t)H_DIM * KC;
    for (size_t idx = (size_t)blockIdx.x * blockDim.x + threadIdx.x; idx < tot;
         idx += (size_t)gridDim.x * blockDim.x) {
        int n = (int)(idx / KC), c = (int)(idx - (size_t)n * KC);
        int k0 = c * 8;
        int e = k0 / INTER, i = k0 - e * INTER;
        const float* sp = w + ((size_t)e * H_DIM + n) * INTER + i;
        float v[8];
        const float4 f0 = *(const float4*)sp;
        const float4 f1 = *(const float4*)(sp + 4);
        v[0]=f0.x; v[1]=f0.y; v[2]=f0.z; v[3]=f0.w; v[4]=f1.x; v[5]=f1.y; v[6]=f1.z; v[7]=f1.w;
        uint4 ph, pl; split8(v, ph, pl);
        size_t off = blk_chunk_off((n >> 7) * KB_FC2 + (c >> 3), n & 127, c & 7);
        *(uint4*)((char*)H + off) = ph;
        *(uint4*)((char*)L + off) = pl;
    }
}

// ---------------------------------------------------------------- rmsnorm (+blocked hi/lo)
__global__ void rmsnorm_kernel(const float* __restrict__ x, const float* __restrict__ w,
                               float* __restrict__ y,
                               __nv_bfloat16* __restrict__ yh, __nv_bfloat16* __restrict__ yl,
                               int W, int xs, int KBk)
{
    int s = blockIdx.x, tid = threadIdx.x;
    const float* xr = x + (size_t)s * xs;
    float ss = 0.f;
    for (int i = tid; i < W; i += 256) { float v = xr[i]; ss += v * v; }
    __shared__ float red[256];
    red[tid] = ss; __syncthreads();
    for (int o = 128; o > 0; o >>= 1) { if (tid < o) red[tid] += red[tid + o]; __syncthreads(); }
    float inv = rsqrtf(red[0] / (float)W + 1e-6f);
    float* yr = y + (size_t)s * W;
    const int KC = W >> 3;
    for (int c = tid; c < KC; c += 256) {
        float v[8];
        #pragma unroll
        for (int j = 0; j < 8; j++) {
            int i = c * 8 + j;
            v[j] = w[i] * xr[i] * inv;
            yr[i] = v[j];
        }
        uint4 ph, pl; split8(v, ph, pl);
        size_t off = blk_chunk_off((s >> 7) * KBk + (c >> 3), s & 127, c & 7);
        *(uint4*)((char*)yh + off) = ph;
        *(uint4*)((char*)yl + off) = pl;
    }
}

// ---------------------------------------------------------------- rope
__global__ void rope_kernel(const int* __restrict__ positions,
                            float* __restrict__ q,
                            const float* __restrict__ ckv,
                            float* __restrict__ kpe)
{
    int s = blockIdx.x;
    float p = (float)positions[s];
    for (int idx = threadIdx.x; idx < NHEAD * 32 + 32; idx += blockDim.x) {
        int j = idx & 31;
        float ang = p * powf(10000.0f, -(float)j * (1.0f / 32.0f));
        float c = cosf(ang), sn = sinf(ang);
        if (idx < NHEAD * 32) {
            int hh = idx >> 5;
            float* xp = q + (size_t)s * H_DIM + hh * DQK + 64;
            float x0 = xp[j], x1 = xp[j + 32];
            xp[j]      = x0 * c - x1 * sn;
            xp[j + 32] = x1 * c + x0 * sn;
        } else {
            const float* xp = ckv + (size_t)s * 320 + 256;
            float x0 = xp[j], x1 = xp[j + 32];
            kpe[(size_t)s * 64 + j]      = x0 * c - x1 * sn;
            kpe[(size_t)s * 64 + j + 32] = x1 * c + x0 * sn;
        }
    }
}

// ---------------------------------------------------------------- gate softmax
__global__ void gate_kernel(const float* __restrict__ x, const float* __restrict__ w,
                            float* __restrict__ probs)
{
    int s = blockIdx.x;
    int warp = threadIdx.x >> 5, lane = threadIdx.x & 31;
    const float* xr = x + (size_t)s * H_DIM;
    const float* wr = w + (size_t)warp * H_DIM;
    float acc = 0.f;
    for (int i = lane; i < H_DIM; i += 32) acc += xr[i] * wr[i];
    #pragma unroll
    for (int o = 16; o; o >>= 1) acc += __shfl_xor_sync(0xffffffffu, acc, o);
    __shared__ float lg[8];
    if (lane == 0) lg[warp] = acc;
    __syncthreads();
    if (threadIdx.x == 0) {
        float mx = lg[0];
        #pragma unroll
        for (int e = 1; e < 8; e++) mx = fmaxf(mx, lg[e]);
        float sum = 0.f, ev[8];
        #pragma unroll
        for (int e = 0; e < 8; e++) { ev[e] = __expf(lg[e] - mx); sum += ev[e]; }
        float invs = 1.f / sum;
        #pragma unroll
        for (int e = 0; e < 8; e++) probs[(size_t)s * 8 + e] = ev[e] * invs;
    }
}

// ---------------------------------------------------------------- SIMT GEMM (kv_a only)
__global__ __launch_bounds__(256, 2) void sgemm_nt(
    const float* __restrict__ A, const float* __restrict__ B,
    float* __restrict__ C, int M, int N, int K)
{
    __shared__ float As[2][16][132];
    __shared__ float Bs[2][16][132];
    const int tid = threadIdx.x;
    const int m0 = blockIdx.y * 128, n0 = blockIdx.x * 128;
    const int r  = tid >> 2;
    const int c4 = (tid & 3) * 4;
    const int ty = tid >> 4, tx = tid & 15;

    const float* Apt = A + (size_t)(m0 + r) * K + c4;
    float4 fa0, fa1, fb0, fb1;
    const float4 z4 = make_float4(0.f, 0.f, 0.f, 0.f);

    auto fetch = [&](int k0) {
        fa0 = *(const float4*)(Apt + k0);
        fa1 = *(const float4*)(Apt + (size_t)64 * K + k0);
        const float* Bp = B + (size_t)(n0 + r) * K + k0 + c4;
        fb0 = (n0 + r      < N) ? *(const float4*)Bp : z4;
        fb1 = (n0 + r + 64 < N) ? *(const float4*)(Bp + (size_t)64 * K) : z4;
    };
    auto stage = [&](int buf) {
        As[buf][c4+0][r]    = fa0.x; As[buf][c4+1][r]    = fa0.y;
        As[buf][c4+2][r]    = fa0.z; As[buf][c4+3][r]    = fa0.w;
        As[buf][c4+0][r+64] = fa1.x; As[buf][c4+1][r+64] = fa1.y;
        As[buf][c4+2][r+64] = fa1.z; As[buf][c4+3][r+64] = fa1.w;
        Bs[buf][c4+0][r]    = fb0.x; Bs[buf][c4+1][r]    = fb0.y;
        Bs[buf][c4+2][r]    = fb0.z; Bs[buf][c4+3][r]    = fb0.w;
        Bs[buf][c4+0][r+64] = fb1.x; Bs[buf][c4+1][r+64] = fb1.y;
        Bs[buf][c4+2][r+64] = fb1.z; Bs[buf][c4+3][r+64] = fb1.w;
    };

    float acc[8][8];
    #pragma unroll
    for (int i = 0; i < 8; i++)
        #pragma unroll
        for (int j = 0; j < 8; j++) acc[i][j] = 0.f;

    fetch(0); stage(0); __syncthreads();
    const int kt = K >> 4;
    int cur = 0;
    for (int t = 0; t < kt; t++) {
        if (t + 1 < kt) fetch((t + 1) << 4);
        #pragma unroll
        for (int kk = 0; kk < 16; kk++) {
            float4 a0 = *(const float4*)&As[cur][kk][ty * 8];
            float4 a1 = *(const float4*)&As[cur][kk][ty * 8 + 4];
            float4 b0 = *(const float4*)&Bs[cur][kk][tx * 8];
            float4 b1 = *(const float4*)&Bs[cur][kk][tx * 8 + 4];
            float a[8] = {a0.x, a0.y, a0.z, a0.w, a1.x, a1.y, a1.z, a1.w};
            float b[8] = {b0.x, b0.y, b0.z, b0.w, b1.x, b1.y, b1.z, b1.w};
            #pragma unroll
            for (int i = 0; i < 8; i++)
                #pragma unroll
                for (int j = 0; j < 8; j++) acc[i][j] = fmaf(a[i], b[j], acc[i][j]);
        }
        if (t + 1 < kt) { stage(cur ^ 1); __syncthreads(); cur ^= 1; }
    }

    #pragma unroll
    for (int i = 0; i < 8; i++) {
        int row = m0 + ty * 8 + i;
        #pragma unroll
        for (int j = 0; j < 8; j++) {
            int col = n0 + tx * 8 + j;
            if (col < N) C[(size_t)row * N + col] = acc[i][j];
        }
    }
}

// ---------------------------------------------------------------- bulk-copy split-bf16 GEMM
// C[M,N] = (Ah+Al) @ (Bh+Bl)^T  (3-term). Operands in blocked/swizzled gmem.
// Tile: 128(M) x 256(N), BK=64. 256 threads, 8 warps (2 M x 4 N), warp = 64x64.
// EPI: 0 plain fp32, 1 silu*probs -> blocked bf16 hi/lo, 2 +extra -> fp32
#define BG_STAGE_B  98304u   // 6 x 16KB
#define BG_SMEM     (1024 + 2 * 98304)
#define OFF_AH 0u
#define OFF_AL 16384u
#define OFF_BH 32768u        // two 16KB B-hi blocks back to back
#define OFF_BL 65536u        // two 16KB B-lo blocks back to back

template<int EPI>
__global__ __launch_bounds__(256, 1) void bgemm(
    const __nv_bfloat16* __restrict__ Abh, const __nv_bfloat16* __restrict__ Abl,
    const __nv_bfloat16* __restrict__ Bbh, const __nv_bfloat16* __restrict__ Bbl,
    int N, int KBk,
    float* __restrict__ C, const float* __restrict__ extra,
    __nv_bfloat16* __restrict__ Ch, __nv_bfloat16* __restrict__ Cl, int CKB)
{
    extern __shared__ char smem[];
    const uint32_t sb = smem_u32(smem);
    const uint32_t tb = (sb + 1023u) & ~1023u;   // stage data, 1KB aligned
    const int tid = threadIdx.x, wid = tid >> 5, lane = tid & 31;
    const int n0 = blockIdx.x * 256, m0 = blockIdx.y * 128;
    const int mb = blockIdx.y, nb0 = blockIdx.x * 2;
    const int wm = (wid >> 2) * 64;          // 0 / 64
    const int wn = (wid & 3) * 64;           // 0..192
    const uint32_t bsel   = (uint32_t)(wn >> 7) * 16384u;  // which B block
    const int     brow0   = wn & 64;                       // row base inside block

    if (tid == 0) { MBAR_INIT(sb, 1); MBAR_INIT(sb + 8, 1); }
    __syncthreads();

    auto load_stage = [&](int t) {
        const int s = t & 1;
        const uint32_t mb_addr = sb + s * 8;
        const uint32_t st = tb + s * BG_STAGE_B;
        MBAR_EXPECT(mb_addr, BG_STAGE_B);
        bulk_g2s(st + OFF_AH,           (const char*)Abh + (((size_t)mb * KBk + t) << 14), 16384u, mb_addr);
        bulk_g2s(st + OFF_AL,           (const char*)Abl + (((size_t)mb * KBk + t) << 14), 16384u, mb_addr);
        bulk_g2s(st + OFF_BH,           (const char*)Bbh + (((size_t)nb0 * KBk + t) << 14), 16384u, mb_addr);
        bulk_g2s(st + OFF_BH + 16384u,  (const char*)Bbh + (((size_t)(nb0 + 1) * KBk + t) << 14), 16384u, mb_addr);
        bulk_g2s(st + OFF_BL,           (const char*)Bbl + (((size_t)nb0 * KBk + t) << 14), 16384u, mb_addr);
        bulk_g2s(st + OFF_BL + 16384u,  (const char*)Bbl + (((size_t)(nb0 + 1) * KBk + t) << 14), 16384u, mb_addr);
    };

    if (tid == 0) { load_stage(0); if (KBk > 1) load_stage(1); }

    float acc[4][8][4];
    #pragma unroll
    for (int i = 0; i < 4; i++)
        #pragma unroll
        for (int j = 0; j < 8; j++)
            #pragma unroll
            for (int k = 0; k < 4; k++) acc[i][j][k] = 0.f;

    const uint32_t a_row = lane & 15, a_chk = lane >> 4;
    const uint32_t b_row = ((lane >> 4) & 1) * 8 + (lane & 7);
    const uint32_t b_chk = (lane >> 3) & 1;

    for (int t = 0; t < KBk; t++) {
        MBAR_WAIT(sb + (t & 1) * 8, (t >> 1) & 1);
        const uint32_t st = tb + (t & 1) * BG_STAGE_B;

        #pragma unroll
        for (int ks = 0; ks < 4; ks++) {
            uint32_t a_h[4][4], a_l[4][4], b_h[8][2], b_l[8][2];
            #pragma unroll
            for (int mt = 0; mt < 4; mt++) {
                uint32_t off = SWZ((uint32_t)(wm + mt * 16 + a_row) * 128u + (ks * 2 + a_chk) * 16u);
                ldsm_x4(a_h[mt], st + OFF_AH + off);
                ldsm_x4(a_l[mt], st + OFF_AL + off);
            }
            #pragma unroll
            for (int p = 0; p < 4; p++) {
                uint32_t off = SWZ((uint32_t)(brow0 + p * 16 + b_row) * 128u + (ks * 2 + b_chk) * 16u);
                uint32_t rh[4], rl[4];
                ldsm_x4(rh, st + OFF_BH + bsel + off);
                ldsm_x4(rl, st + OFF_BL + bsel + off);
                b_h[2*p][0]=rh[0]; b_h[2*p][1]=rh[1]; b_h[2*p+1][0]=rh[2]; b_h[2*p+1][1]=rh[3];
                b_l[2*p][0]=rl[0]; b_l[2*p][1]=rl[1]; b_l[2*p+1][0]=rl[2]; b_l[2*p+1][1]=rl[3];
            }
            #pragma unroll
            for (int mt = 0; mt < 4; mt++)
                #pragma unroll
                for (int nt = 0; nt < 8; nt++) {
                    mma_bf16(acc[mt][nt], a_h[mt], b_h[nt]);
                    mma_bf16(acc[mt][nt], a_h[mt], b_l[nt]);
                    mma_bf16(acc[mt][nt], a_l[mt], b_h[nt]);
                }
        }
        __syncthreads();
        if (tid == 0 && t + 2 < KBk) load_stage(t + 2);
    }

    // ---------------- epilogue
    #pragma unroll
    for (int mt = 0; mt < 4; mt++) {
        #pragma unroll
        for (int half = 0; half < 2; half++) {
            const int row = m0 + wm + mt * 16 + half * 8 + (lane >> 2);
            #pragma unroll
            for (int nt = 0; nt < 8; nt++) {
                const int col = n0 + wn + nt * 8 + (lane & 3) * 2;
                float v0 = acc[mt][nt][half * 2 + 0];
                float v1 = acc[mt][nt][half * 2 + 1];
                if (EPI == 0) {
                    *(float2*)&C[(size_t)row * N + col] = make_float2(v0, v1);
                } else if (EPI == 2) {
                    const float2 e2 = *(const float2*)&extra[(size_t)row * N + col];
                    *(float2*)&C[(size_t)row * N + col] = make_float2(v0 + e2.x, v1 + e2.y);
                } else {
                    float pf = extra[(size_t)row * NEXP + (col / INTER)];
                    float s0 = v0 / (1.f + __expf(-v0)) * pf;
                    float s1 = v1 / (1.f + __expf(-v1)) * pf;
                    __nv_bfloat16 h0 = __float2bfloat16(s0);
                    __nv_bfloat16 h1 = __float2bfloat16(s1);
                    uint32_t ph = (uint32_t)__bfloat16_as_ushort(h0) |
                                  ((uint32_t)__bfloat16_as_ushort(h1) << 16);
                    uint32_t pl = (uint32_t)__bfloat16_as_ushort(__float2bfloat16(s0 - __bfloat162float(h0))) |
                                  ((uint32_t)__bfloat16_as_ushort(__float2bfloat16(s1 - __bfloat162float(h1))) << 16);
                    uint32_t inner = (uint32_t)(row & 127) * 128u + (uint32_t)(col & 63) * 2u;
                    size_t off = (((size_t)(row >> 7) * CKB + (col >> 6)) << 14) + SWZ(inner);
                    *(uint32_t*)((char*)Ch + off) = ph;
                    *(uint32_t*)((char*)Cl + off) = pl;
                }
            }
        }
    }
}

// ---------------------------------------------------------------- attention (SIMT flash)
#define ATTN_SMEM ((2 * 128 * 68 + 64 * 64 + 64 * 68) * 4)

__global__ __launch_bounds__(256) void attn_kernel(
    const float* __restrict__ q, const float* __restrict__ kv,
    const float* __restrict__ kpe,
    __nv_bfloat16* __restrict__ ctxh, __nv_bfloat16* __restrict__ ctxl)
{
    extern __shared__ float sm[];
    float (*Qt)[68] = reinterpret_cast<float(*)[68]>(sm);
    float (*Kt)[68] = reinterpret_cast<float(*)[68]>(sm + 128 * 68);
    float (*Vs)[64] = reinterpret_cast<float(*)[64]>(sm + 2 * 128 * 68);
    float (*Pt)[68] = reinterpret_cast<float(*)[68]>(sm + 2 * 128 * 68 + 64 * 64);

    const int h  = blockIdx.y;
    const int qi = (int)gridDim.x - 1 - (int)blockIdx.x;
    const int q0 = qi * 64;
    const int tid = threadIdx.x;
    const int ty = tid >> 4, tx = tid & 15;

    for (int i = tid; i < 64 * 128; i += 256) {
        int r = i >> 7, d = i & 127;
        Qt[d][r] = q[(size_t)(q0 + r) * H_DIM + h * DQK + d];
    }

    float m_i[4], l_i[4], o[4][4];
    #pragma unroll
    for (int i = 0; i < 4; i++) {
        m_i[i] = -1e30f; l_i[i] = 0.f;
        #pragma unroll
        for (int j = 0; j < 4; j++) o[i][j] = 0.f;
    }
    const float SC = 0.08838834764831845f;

    for (int kt = 0; kt <= qi; kt++) {
        const int k0 = kt * 64;
        __syncthreads();
        for (int i = tid; i < 64 * 128; i += 256) {
            int r = i >> 7, d = i & 127;
            Kt[d][r] = (d < 64) ? kv[(size_t)(k0 + r) * H_DIM + h * DQK + d]
                                : kpe[(size_t)(k0 + r) * 64 + (d - 64)];
        }
        for (int i = tid; i < 64 * 64; i += 256) {
            int r = i >> 6, c = i & 63;
            Vs[r][c] = kv[(size_t)(k0 + r) * H_DIM + h * DQK + 64 + c];
        }
        __syncthreads();

        float s4[4][4];
        #pragma unroll
        for (int i = 0; i < 4; i++)
            #pragma unroll
            for (int j = 0; j < 4; j++) s4[i][j] = 0.f;

        #pragma unroll 8
        for (int kk = 0; kk < 128; kk++) {
            float4 av = *(const float4*)&Qt[kk][ty * 4];
            float4 bv = *(const float4*)&Kt[kk][tx * 4];
            float a[4] = {av.x, av.y, av.z, av.w};
            float b[4] = {bv.x, bv.y, bv.z, bv.w};
            #pragma unroll
            for (int i = 0; i < 4; i++)
                #pragma unroll
                for (int j = 0; j < 4; j++) s4[i][j] = fmaf(a[i], b[j], s4[i][j]);
        }

        const bool diag = (kt == qi);
        #pragma unroll
        for (int i = 0; i < 4; i++) {
            float mx = -1e30f;
            #pragma unroll
            for (int j = 0; j < 4; j++) {
                float v = s4[i][j] * SC;
                if (diag && (tx * 4 + j) > (ty * 4 + i)) v = -1e30f;
                s4[i][j] = v;
                mx = fmaxf(mx, v);
            }
            #pragma unroll
            for (int off = 8; off; off >>= 1)
                mx = fmaxf(mx, __shfl_xor_sync(0xffffffffu, mx, off));
            float mnew = fmaxf(m_i[i], mx);
            float rs = 0.f;
            #pragma unroll
            for (int j = 0; j < 4; j++) {
                float pv = __expf(s4[i][j] - mnew);
                s4[i][j] = pv; rs += pv;
            }
            #pragma unroll
            for (int off = 8; off; off >>= 1)
                rs += __shfl_xor_sync(0xffffffffu, rs, off);
            float corr = __expf(m_i[i] - mnew);
            l_i[i] = l_i[i] * corr + rs;
            m_i[i] = mnew;
            #pragma unroll
            for (int j = 0; j < 4; j++) o[i][j] *= corr;
        }
        #pragma unroll
        for (int i = 0; i < 4; i++)
            #pragma unroll
            for (int j = 0; j < 4; j++) Pt[tx * 4 + j][ty * 4 + i] = s4[i][j];
        __syncthreads();

        #pragma unroll 8
        for (int kk = 0; kk < 64; kk++) {
            float4 av = *(const float4*)&Pt[kk][ty * 4];
            float4 bv = *(const float4*)&Vs[kk][tx * 4];
            float a[4] = {av.x, av.y, av.z, av.w};
            float b[4] = {bv.x, bv.y, bv.z, bv.w};
            #pragma unroll
            for (int i = 0; i < 4; i++)
                #pragma unroll
                for (int j = 0; j < 4; j++) o[i][j] = fmaf(a[i], b[j], o[i][j]);
        }
    }

    // write ctx in blocked hi/lo layout (K = NHEAD*DV = 1024, KB_CTX = 16)
    #pragma unroll
    for (int i = 0; i < 4; i++) {
        float inv = 1.f / l_i[i];
        uint32_t hh[4], ll[4];
        #pragma unroll
        for (int j = 0; j < 4; j++) {
            float v = o[i][j] * inv;
            __nv_bfloat16 hb = __float2bfloat16(v);
            hh[j] = (uint32_t)__bfloat16_as_ushort(hb);
            ll[j] = (uint32_t)__bfloat16_as_ushort(__float2bfloat16(v - __bfloat162float(hb)));
        }
        const int row = q0 + ty * 4 + i;
        const int col = h * DV + tx * 4;
        uint32_t inner = (uint32_t)(row & 127) * 128u + (uint32_t)(col & 63) * 2u;
        size_t off = (((size_t)(row >> 7) * KB_CTX + (col >> 6)) << 14) + SWZ(inner);
        *(uint2*)((char*)ctxh + off) = make_uint2(hh[0] | (hh[1] << 16), hh[2] | (hh[3] << 16));
        *(uint2*)((char*)ctxl + off) = make_uint2(ll[0] | (ll[1] << 16), ll[2] | (ll[3] << 16));
    }
}

// ---------------------------------------------------------------- launch
extern "C" void kernel_launch(void* const* d_in, const int* in_sizes, int n_in,
                              void* d_out, int out_size)
{
    const int*   positions = (const int*)  d_in[0];
    const float* hidden    = (const float*)d_in[1];
    const float* in_ln     = (const float*)d_in[2];
    const float* qw        = (const float*)d_in[3];
    const float* kva_w     = (const float*)d_in[4];
    const float* kvaln     = (const float*)d_in[5];
    const float* kvb_w     = (const float*)d_in[6];
    const float* ow        = (const float*)d_in[7];
    const float* postln    = (const float*)d_in[8];
    const float* gatew     = (const float*)d_in[9];
    const float* fc1w      = (const float*)d_in[10];
    const float* fc2w      = (const float*)d_in[11];
    float* out = (float*)d_out;

    float *sa, *qb, *ckv, *kvn, *kvv, *kpe, *x2, *mlp, *pr;
    cudaGetSymbolAddress((void**)&sa,  g_sa);
    cudaGetSymbolAddress((void**)&qb,  g_q);
    cudaGetSymbolAddress((void**)&ckv, g_ckv);
    cudaGetSymbolAddress((void**)&kvn, g_kvn);
    cudaGetSymbolAddress((void**)&kvv, g_kv);
    cudaGetSymbolAddress((void**)&kpe, g_kpe);
    cudaGetSymbolAddress((void**)&x2,  g_x2);
    cudaGetSymbolAddress((void**)&mlp, g_mlp);
    cudaGetSymbolAddress((void**)&pr,  g_pr);

    __nv_bfloat16 *sah,*sal,*kvnh,*kvnl,*mlph,*mlpl,*ctxh,*ctxl,*hbh,*hbl;
    __nv_bfloat16 *qwh,*qwl,*kbwh,*kbwl,*owh,*owl,*f1h,*f1l,*f2h,*f2l;
    cudaGetSymbolAddress((void**)&sah,  g_sa_h);  cudaGetSymbolAddress((void**)&sal,  g_sa_l);
    cudaGetSymbolAddress((void**)&kvnh, g_kvn_h); cudaGetSymbolAddress((void**)&kvnl, g_kvn_l);
    cudaGetSymbolAddress((void**)&mlph, g_mlp_h); cudaGetSymbolAddress((void**)&mlpl, g_mlp_l);
    cudaGetSymbolAddress((void**)&ctxh, g_ctx_h); cudaGetSymbolAddress((void**)&ctxl, g_ctx_l);
    cudaGetSymbolAddress((void**)&hbh,  g_hb_h);  cudaGetSymbolAddress((void**)&hbl,  g_hb_l);
    cudaGetSymbolAddress((void**)&qwh,  g_qw_h);  cudaGetSymbolAddress((void**)&qwl,  g_qw_l);
    cudaGetSymbolAddress((void**)&kbwh, g_kbw_h); cudaGetSymbolAddress((void**)&kbwl, g_kbw_l);
    cudaGetSymbolAddress((void**)&owh,  g_ow_h);  cudaGetSymbolAddress((void**)&owl,  g_ow_l);
    cudaGetSymbolAddress((void**)&f1h,  g_f1_h);  cudaGetSymbolAddress((void**)&f1l,  g_f1_l);
    cudaGetSymbolAddress((void**)&f2h,  g_f2_h);  cudaGetSymbolAddress((void**)&f2l,  g_f2_l);

    cudaFuncSetAttribute(bgemm<0>, cudaFuncAttributeMaxDynamicSharedMemorySize, BG_SMEM);
    cudaFuncSetAttribute(bgemm<1>, cudaFuncAttributeMaxDynamicSharedMemorySize, BG_SMEM);
    cudaFuncSetAttribute(bgemm<2>, cudaFuncAttributeMaxDynamicSharedMemorySize, BG_SMEM);
    cudaFuncSetAttribute(attn_kernel, cudaFuncAttributeMaxDynamicSharedMemorySize, ATTN_SMEM);

    // weight converts -> blocked hi/lo
    cvt_blk_kernel<<<2048, 256>>>(qw,    qwh,  qwl,  H_DIM, H_DIM);
    cvt_blk_kernel<<<512,  256>>>(kvb_w, kbwh, kbwl, H_DIM, KVR);
    cvt_blk_kernel<<<1024, 256>>>(ow,    owh,  owl,  H_DIM, NHEAD * DV);
    cvt_blk_kernel<<<4096, 256>>>(fc1w,  f1h,  f1l,  NFC1, H_DIM);
    cvt_fc2_blk_kernel<<<4096, 256>>>(fc2w, f2h, f2l);

    // 1. input RMSNorm (fp32 + blocked hi/lo)
    rmsnorm_kernel<<<S_LEN, 256>>>(hidden, in_ln, sa, sah, sal, H_DIM, H_DIM, KB_H);
    // 2. q projection
    bgemm<0><<<dim3(8, 16), 256, BG_SMEM>>>(sah, sal, qwh, qwl, H_DIM, KB_H,
        qb, nullptr, nullptr, nullptr, 0);
    // 3. kv_a projection (SIMT, N=320)
    sgemm_nt<<<dim3(3, 16), 256>>>(sa, kva_w, ckv, S_LEN, 320, H_DIM);
    // 4. kv RMSNorm
    rmsnorm_kernel<<<S_LEN, 256>>>(ckv, kvaln, kvn, kvnh, kvnl, KVR, 320, KB_KVR);
    // 5. kv_b projection
    bgemm<0><<<dim3(8, 16), 256, BG_SMEM>>>(kvnh, kvnl, kbwh, kbwl, H_DIM, KB_KVR,
        kvv, nullptr, nullptr, nullptr, 0);
    // 6. RoPE
    rope_kernel<<<S_LEN, 256>>>(positions, qb, ckv, kpe);
    // 7. attention (writes blocked ctx hi/lo)
    attn_kernel<<<dim3(S_LEN / 64, NHEAD), 256, ATTN_SMEM>>>(qb, kvv, kpe, ctxh, ctxl);
    // 8. o projection + residual
    bgemm<2><<<dim3(8, 16), 256, BG_SMEM>>>(ctxh, ctxl, owh, owl, H_DIM, KB_CTX,
        x2, hidden, nullptr, nullptr, 0);
    // 9. post RMSNorm
    rmsnorm_kernel<<<S_LEN, 256>>>(x2, postln, mlp, mlph, mlpl, H_DIM, H_DIM, KB_H);
    // 10. gate softmax
    gate_kernel<<<S_LEN, 256>>>(mlp, gatew, pr);
    // 11. fc1 + SiLU*probs -> blocked hbuf hi/lo
    bgemm<1><<<dim3(NFC1 / 256, 16), 256, BG_SMEM>>>(mlph, mlpl, f1h, f1l, NFC1, KB_H,
        nullptr, pr, hbh, hbl, KB_FC2);
    // 12. fc2 + residual -> out
    bgemm<2><<<dim3(8, 16), 256, BG_SMEM>>>(hbh, hbl, f2h, f2l, H_DIM, KB_FC2,
        out, x2, nullptr, nullptr, 0);
}

// round 5
// speedup vs baseline: 3.3888x; 1.3652x over previous
#include <cuda_runtime.h>
#include <cuda_bf16.h>
#include <math.h>
#include <stdint.h>

// ---------------------------------------------------------------- constants
#define S_LEN 2048
#define H_DIM 2048
#define NHEAD 16
#define DQK   128
#define DV    64
#define KVR   256
#define NEXP  8
#define INTER 1408
#define NFC1  (NEXP*INTER)   // 11264
#define CKV_P 512            // padded kv_a output width

#define KB_H    (H_DIM/64)      // 32
#define KB_KVR  (KVR/64)        // 4
#define KB_CTX  ((NHEAD*DV)/64) // 16
#define KB_FC2  (NFC1/64)       // 176

// ---------------------------------------------------------------- scratch (fp32)
__device__ float g_sa  [S_LEN*H_DIM];
__device__ float g_q   [S_LEN*H_DIM];
__device__ float g_ckv [S_LEN*CKV_P];
__device__ float g_kvn [S_LEN*KVR];
__device__ float g_kv  [S_LEN*H_DIM];
__device__ float g_kpe [S_LEN*64];
__device__ float g_x2  [S_LEN*H_DIM];
__device__ float g_mlp [S_LEN*H_DIM];
__device__ float g_pr  [S_LEN*NEXP];

// ---------------------------------------------------------------- scratch (blocked bf16 hi/lo)
__device__ __nv_bfloat16 g_sa_h [S_LEN*H_DIM],   g_sa_l [S_LEN*H_DIM];
__device__ __nv_bfloat16 g_kvn_h[S_LEN*KVR],     g_kvn_l[S_LEN*KVR];
__device__ __nv_bfloat16 g_mlp_h[S_LEN*H_DIM],   g_mlp_l[S_LEN*H_DIM];
__device__ __nv_bfloat16 g_ctx_h[S_LEN*NHEAD*DV],g_ctx_l[S_LEN*NHEAD*DV];
__device__ __nv_bfloat16 g_hb_h [(size_t)S_LEN*NFC1], g_hb_l [(size_t)S_LEN*NFC1];
__device__ __nv_bfloat16 g_qw_h [H_DIM*H_DIM],   g_qw_l [H_DIM*H_DIM];
__device__ __nv_bfloat16 g_kva_h[CKV_P*H_DIM],   g_kva_l[CKV_P*H_DIM];
__device__ __nv_bfloat16 g_kbw_h[H_DIM*KVR],     g_kbw_l[H_DIM*KVR];
__device__ __nv_bfloat16 g_ow_h [H_DIM*NHEAD*DV],g_ow_l [H_DIM*NHEAD*DV];
__device__ __nv_bfloat16 g_f1_h [(size_t)NFC1*H_DIM], g_f1_l [(size_t)NFC1*H_DIM];
__device__ __nv_bfloat16 g_f2_h [(size_t)H_DIM*NFC1], g_f2_l [(size_t)H_DIM*NFC1];
// attention operands (head-blocked)
__device__ __nv_bfloat16 g_qb_h[S_LEN*H_DIM],    g_qb_l[S_LEN*H_DIM];
__device__ __nv_bfloat16 g_kb_h[S_LEN*H_DIM],    g_kb_l[S_LEN*H_DIM];
__device__ __nv_bfloat16 g_vt_h[S_LEN*NHEAD*DV], g_vt_l[S_LEN*NHEAD*DV];

// ---------------------------------------------------------------- helpers
__device__ __forceinline__ uint32_t smem_u32(const void* p) {
    uint32_t a;
    asm("{ .reg .u64 t; cvta.to.shared.u64 t, %1; cvt.u32.u64 %0, t; }" : "=r"(a) : "l"(p));
    return a;
}
#define SWZ(off) ((off) ^ (((off) >> 3) & 0x70u))

__device__ __forceinline__ void ldsm_x4(uint32_t* r, uint32_t addr) {
    asm volatile("ldmatrix.sync.aligned.m8n8.x4.shared.b16 {%0,%1,%2,%3}, [%4];"
                 : "=r"(r[0]), "=r"(r[1]), "=r"(r[2]), "=r"(r[3]) : "r"(addr));
}
__device__ __forceinline__ void mma_bf16(float* c, const uint32_t* a, const uint32_t* b) {
    asm volatile("mma.sync.aligned.m16n8k16.row.col.f32.bf16.bf16.f32 "
                 "{%0,%1,%2,%3}, {%4,%5,%6,%7}, {%8,%9}, {%0,%1,%2,%3};"
                 : "+f"(c[0]), "+f"(c[1]), "+f"(c[2]), "+f"(c[3])
                 : "r"(a[0]), "r"(a[1]), "r"(a[2]), "r"(a[3]), "r"(b[0]), "r"(b[1]));
}
#define MBAR_INIT(a, c) asm volatile("mbarrier.init.shared.b64 [%0], %1;" :: "r"(a), "r"(c) : "memory")
#define MBAR_EXPECT(a, b) asm volatile("mbarrier.arrive.expect_tx.shared.b64 _, [%0], %1;" :: "r"(a), "r"(b) : "memory")
#define MBAR_WAIT(a, ph) do { \
    asm volatile("{\n\t.reg .pred P1;\n\tWL_%=:\n\t" \
        "mbarrier.try_wait.parity.acquire.cta.shared::cta.b64 P1, [%0], %1, 0x989680;\n\t" \
        "@P1 bra.uni WD_%=;\n\tbra.uni WL_%=;\n\tWD_%=:\n\t}" \
        :: "r"(a), "r"(ph) : "memory"); } while (0)
__device__ __forceinline__ void bulk_g2s(uint32_t dst, const void* src, uint32_t bytes, uint32_t mbar) {
    asm volatile("cp.async.bulk.shared::cluster.global.mbarrier::complete_tx::bytes [%0], [%1], %2, [%3];"
                 :: "r"(dst), "l"(src), "r"(bytes), "r"(mbar) : "memory");
}

__device__ __forceinline__ uint32_t pack_hilo(float x, float y, uint32_t& lo) {
    __nv_bfloat16 hx = __float2bfloat16(x), hy = __float2bfloat16(y);
    __nv_bfloat16 lx = __float2bfloat16(x - __bfloat162float(hx));
    __nv_bfloat16 ly = __float2bfloat16(y - __bfloat162float(hy));
    lo = (uint32_t)__bfloat16_as_ushort(lx) | ((uint32_t)__bfloat16_as_ushort(ly) << 16);
    return (uint32_t)__bfloat16_as_ushort(hx) | ((uint32_t)__bfloat16_as_ushort(hy) << 16);
}
__device__ __forceinline__ void split8(const float* v, uint4& ph, uint4& pl) {
    uint32_t hh[8], ll[8];
    #pragma unroll
    for (int j = 0; j < 8; j++) {
        __nv_bfloat16 h = __float2bfloat16(v[j]);
        __nv_bfloat16 l = __float2bfloat16(v[j] - __bfloat162float(h));
        hh[j] = (uint32_t)__bfloat16_as_ushort(h);
        ll[j] = (uint32_t)__bfloat16_as_ushort(l);
    }
    ph = make_uint4(hh[0]|(hh[1]<<16), hh[2]|(hh[3]<<16), hh[4]|(hh[5]<<16), hh[6]|(hh[7]<<16));
    pl = make_uint4(ll[0]|(ll[1]<<16), ll[2]|(ll[3]<<16), ll[4]|(ll[5]<<16), ll[6]|(ll[7]<<16));
}
__device__ __forceinline__ size_t blk_chunk_off(int blk_idx, int row, int c8) {
    uint32_t inner = (uint32_t)row * 128u + (uint32_t)c8 * 16u;
    return ((size_t)blk_idx << 14) + SWZ(inner);
}

// ---------------------------------------------------------------- weight converts
__global__ void cvt_blk_kernel(const float* __restrict__ src,
                               __nv_bfloat16* __restrict__ H, __nv_bfloat16* __restrict__ L,
                               int Npad, int Nreal, int K) {
    const int KC = K >> 3;
    const int KBk = K >> 6;
    const size_t tot = (size_t)Npad * KC;
    for (size_t idx = (size_t)blockIdx.x * blockDim.x + threadIdx.x; idx < tot;
         idx += (size_t)gridDim.x * blockDim.x) {
        int n = (int)(idx / KC), c = (int)(idx - (size_t)n * KC);
        float v[8];
        if (n < Nreal) {
            const float4 f0 = *(const float4*)(src + (size_t)n * K + c * 8);
            const float4 f1 = *(const float4*)(src + (size_t)n * K + c * 8 + 4);
            v[0]=f0.x; v[1]=f0.y; v[2]=f0.z; v[3]=f0.w; v[4]=f1.x; v[5]=f1.y; v[6]=f1.z; v[7]=f1.w;
        } else {
            #pragma unroll
            for (int j = 0; j < 8; j++) v[j] = 0.f;
        }
        uint4 ph, pl; split8(v, ph, pl);
        size_t off = blk_chunk_off((n >> 7) * KBk + (c >> 3), n & 127, c & 7);
        *(uint4*)((char*)H + off) = ph;
        *(uint4*)((char*)L + off) = pl;
    }
}

__global__ void cvt_fc2_blk_kernel(const float* __restrict__ w,
                                   __nv_bfloat16* __restrict__ H, __nv_bfloat16* __restrict__ L) {
    const int KC = NFC1 >> 3;
    const size_t tot = (size_t)H_DIM * KC;
    for (size_t idx = (size_t)blockIdx.x * blockDim.x + threadIdx.x; idx < tot;
         idx += (size_t)gridDim.x * blockDim.x) {
        int n = (int)(idx / KC), c = (int)(idx - (size_t)n * KC);
        int k0 = c * 8;
        int e = k0 / INTER, i = k0 - e * INTER;
        const float* sp = w + ((size_t)e * H_DIM + n) * INTER + i;
        float v[8];
        const float4 f0 = *(const float4*)sp;
        const float4 f1 = *(const float4*)(sp + 4);
        v[0]=f0.x; v[1]=f0.y; v[2]=f0.z; v[3]=f0.w; v[4]=f1.x; v[5]=f1.y; v[6]=f1.z; v[7]=f1.w;
        uint4 ph, pl; split8(v, ph, pl);
        size_t off = blk_chunk_off((n >> 7) * KB_FC2 + (c >> 3), n & 127, c & 7);
        *(uint4*)((char*)H + off) = ph;
        *(uint4*)((char*)L + off) = pl;
    }
}

// ---------------------------------------------------------------- rmsnorm (+blocked hi/lo)
__global__ void rmsnorm_kernel(const float* __restrict__ x, const float* __restrict__ w,
                               float* __restrict__ y,
                               __nv_bfloat16* __restrict__ yh, __nv_bfloat16* __restrict__ yl,
                               int W, int xs, int KBk)
{
    int s = blockIdx.x, tid = threadIdx.x;
    const float* xr = x + (size_t)s * xs;
    float ss = 0.f;
    for (int i = tid; i < W; i += 256) { float v = xr[i]; ss += v * v; }
    __shared__ float red[256];
    red[tid] = ss; __syncthreads();
    for (int o = 128; o > 0; o >>= 1) { if (tid < o) red[tid] += red[tid + o]; __syncthreads(); }
    float inv = rsqrtf(red[0] / (float)W + 1e-6f);
    float* yr = y + (size_t)s * W;
    const int KC = W >> 3;
    for (int c = tid; c < KC; c += 256) {
        float v[8];
        #pragma unroll
        for (int j = 0; j < 8; j++) {
            int i = c * 8 + j;
            v[j] = w[i] * xr[i] * inv;
            yr[i] = v[j];
        }
        uint4 ph, pl; split8(v, ph, pl);
        size_t off = blk_chunk_off((s >> 7) * KBk + (c >> 3), s & 127, c & 7);
        *(uint4*)((char*)yh + off) = ph;
        *(uint4*)((char*)yl + off) = pl;
    }
}

// ---------------------------------------------------------------- rope
__global__ void rope_kernel(const int* __restrict__ positions,
                            float* __restrict__ q,
                            const float* __restrict__ ckv,
                            float* __restrict__ kpe)
{
    int s = blockIdx.x;
    float p = (float)positions[s];
    for (int idx = threadIdx.x; idx < NHEAD * 32 + 32; idx += blockDim.x) {
        int j = idx & 31;
        float ang = p * powf(10000.0f, -(float)j * (1.0f / 32.0f));
        float c = cosf(ang), sn = sinf(ang);
        if (idx < NHEAD * 32) {
            int hh = idx >> 5;
            float* xp = q + (size_t)s * H_DIM + hh * DQK + 64;
            float x0 = xp[j], x1 = xp[j + 32];
            xp[j]      = x0 * c - x1 * sn;
            xp[j + 32] = x1 * c + x0 * sn;
        } else {
            const float* xp = ckv + (size_t)s * CKV_P + 256;
            float x0 = xp[j], x1 = xp[j + 32];
            kpe[(size_t)s * 64 + j]      = x0 * c - x1 * sn;
            kpe[(size_t)s * 64 + j + 32] = x1 * c + x0 * sn;
        }
    }
}

// ---------------------------------------------------------------- gate softmax
__global__ void gate_kernel(const float* __restrict__ x, const float* __restrict__ w,
                            float* __restrict__ probs)
{
    int s = blockIdx.x;
    int warp = threadIdx.x >> 5, lane = threadIdx.x & 31;
    const float* xr = x + (size_t)s * H_DIM;
    const float* wr = w + (size_t)warp * H_DIM;
    float acc = 0.f;
    for (int i = lane; i < H_DIM; i += 32) acc += xr[i] * wr[i];
    #pragma unroll
    for (int o = 16; o; o >>= 1) acc += __shfl_xor_sync(0xffffffffu, acc, o);
    __shared__ float lg[8];
    if (lane == 0) lg[warp] = acc;
    __syncthreads();
    if (threadIdx.x == 0) {
        float mx = lg[0];
        #pragma unroll
        for (int e = 1; e < 8; e++) mx = fmaxf(mx, lg[e]);
        float sum = 0.f, ev[8];
        #pragma unroll
        for (int e = 0; e < 8; e++) { ev[e] = __expf(lg[e] - mx); sum += ev[e]; }
        float invs = 1.f / sum;
        #pragma unroll
        for (int e = 0; e < 8; e++) probs[(size_t)s * 8 + e] = ev[e] * invs;
    }
}

// ---------------------------------------------------------------- attention input converts
// q fp32 (post-rope) -> head-blocked hi/lo; K = concat(kv nope, kpe) -> head-blocked
__global__ void qk_cvt_kernel(const float* __restrict__ q, const float* __restrict__ kv,
                              const float* __restrict__ kpe,
                              __nv_bfloat16* __restrict__ QH, __nv_bfloat16* __restrict__ QL,
                              __nv_bfloat16* __restrict__ KH, __nv_bfloat16* __restrict__ KL)
{
    const int s = blockIdx.x, tid = threadIdx.x;
    const int h = tid >> 4, d = (tid & 15) * 8;
    // block index for (h, s-block, d-block): ((h*16 + sb)*2 + db)
    const size_t off = ((size_t)((h * 16 + (s >> 7)) * 2 + (d >> 6)) << 14)
                       + SWZ((uint32_t)(s & 127) * 128u + (uint32_t)(d & 63) * 2u);
    {
        float v[8];
        #pragma unroll
        for (int j = 0; j < 8; j++) v[j] = q[(size_t)s * H_DIM + h * DQK + d + j];
        uint4 ph, pl; split8(v, ph, pl);
        *(uint4*)((char*)QH + off) = ph;
        *(uint4*)((char*)QL + off) = pl;
    }
    {
        float v[8];
        #pragma unroll
        for (int j = 0; j < 8; j++) {
            int dd = d + j;
            v[j] = (dd < 64) ? kv[(size_t)s * H_DIM + h * DQK + dd]
                             : kpe[(size_t)s * 64 + dd - 64];
        }
        uint4 ph, pl; split8(v, ph, pl);
        *(uint4*)((char*)KH + off) = ph;
        *(uint4*)((char*)KL + off) = pl;
    }
}

// V transpose: Vt[h][sb]: 16KB = two 8KB sub-blocks (64 d rows x 64 s cols each)
__global__ void vt_cvt_kernel(const float* __restrict__ kv,
                              __nv_bfloat16* __restrict__ VH, __nv_bfloat16* __restrict__ VL)
{
    __shared__ float vt[128][65];
    const int sb = blockIdx.x, h = blockIdx.y, tid = threadIdx.x;
    // load 128 s x 64 d
    #pragma unroll
    for (int i = 0; i < 32; i++) {
        int idx = tid + i * 256;
        int r = idx >> 6, c = idx & 63;
        vt[r][c] = kv[(size_t)(sb * 128 + r) * H_DIM + h * DQK + 64 + c];
    }
    __syncthreads();
    // write transposed: d rows, s chunks of 8
    #pragma unroll
    for (int i = 0; i < 4; i++) {
        int idx = tid + i * 256;
        int d = idx >> 4, s0 = (idx & 15) * 8;
        float v[8];
        #pragma unroll
        for (int j = 0; j < 8; j++) v[j] = vt[s0 + j][d];
        uint4 ph, pl; split8(v, ph, pl);
        size_t off = ((size_t)(h * 16 + sb) << 14) + (size_t)(s0 >> 6) * 8192u
                     + SWZ((uint32_t)d * 128u + (uint32_t)(s0 & 63) * 2u);
        *(uint4*)((char*)VH + off) = ph;
        *(uint4*)((char*)VL + off) = pl;
    }
}

// ---------------------------------------------------------------- bulk-copy split-bf16 GEMM
#define BG_STAGE_B  98304u
#define BG_SMEM     (1024 + 2 * 98304)
#define OFF_AH 0u
#define OFF_AL 16384u
#define OFF_BH 32768u
#define OFF_BL 65536u

template<int EPI>
__global__ __launch_bounds__(256, 1) void bgemm(
    const __nv_bfloat16* __restrict__ Abh, const __nv_bfloat16* __restrict__ Abl,
    const __nv_bfloat16* __restrict__ Bbh, const __nv_bfloat16* __restrict__ Bbl,
    int N, int KBk,
    float* __restrict__ C, const float* __restrict__ extra,
    __nv_bfloat16* __restrict__ Ch, __nv_bfloat16* __restrict__ Cl, int CKB)
{
    extern __shared__ char smem[];
    const uint32_t sb = smem_u32(smem);
    const uint32_t tb = (sb + 1023u) & ~1023u;
    const int tid = threadIdx.x, wid = tid >> 5, lane = tid & 31;
    const int n0 = blockIdx.x * 256, m0 = blockIdx.y * 128;
    const int mb = blockIdx.y, nb0 = blockIdx.x * 2;
    const int wm = (wid >> 2) * 64;
    const int wn = (wid & 3) * 64;
    const uint32_t bsel = (uint32_t)(wn >> 7) * 16384u;
    const int brow0 = wn & 64;

    if (tid == 0) { MBAR_INIT(sb, 1); MBAR_INIT(sb + 8, 1); }
    __syncthreads();

    auto load_stage = [&](int t) {
        const int s = t & 1;
        const uint32_t mb_addr = sb + s * 8;
        const uint32_t st = tb + s * BG_STAGE_B;
        MBAR_EXPECT(mb_addr, BG_STAGE_B);
        bulk_g2s(st + OFF_AH,          (const char*)Abh + (((size_t)mb * KBk + t) << 14), 16384u, mb_addr);
        bulk_g2s(st + OFF_AL,          (const char*)Abl + (((size_t)mb * KBk + t) << 14), 16384u, mb_addr);
        bulk_g2s(st + OFF_BH,          (const char*)Bbh + (((size_t)nb0 * KBk + t) << 14), 16384u, mb_addr);
        bulk_g2s(st + OFF_BH + 16384u, (const char*)Bbh + (((size_t)(nb0 + 1) * KBk + t) << 14), 16384u, mb_addr);
        bulk_g2s(st + OFF_BL,          (const char*)Bbl + (((size_t)nb0 * KBk + t) << 14), 16384u, mb_addr);
        bulk_g2s(st + OFF_BL + 16384u, (const char*)Bbl + (((size_t)(nb0 + 1) * KBk + t) << 14), 16384u, mb_addr);
    };

    if (tid == 0) { load_stage(0); if (KBk > 1) load_stage(1); }

    float acc[4][8][4];
    #pragma unroll
    for (int i = 0; i < 4; i++)
        #pragma unroll
        for (int j = 0; j < 8; j++)
            #pragma unroll
            for (int k = 0; k < 4; k++) acc[i][j][k] = 0.f;

    const uint32_t a_row = lane & 15, a_chk = lane >> 4;
    const uint32_t b_row = ((lane >> 4) & 1) * 8 + (lane & 7);
    const uint32_t b_chk = (lane >> 3) & 1;

    for (int t = 0; t < KBk; t++) {
        MBAR_WAIT(sb + (t & 1) * 8, (t >> 1) & 1);
        const uint32_t st = tb + (t & 1) * BG_STAGE_B;

        #pragma unroll
        for (int ks = 0; ks < 4; ks++) {
            uint32_t a_h[4][4], a_l[4][4], b_h[8][2], b_l[8][2];
            #pragma unroll
            for (int mt = 0; mt < 4; mt++) {
                uint32_t off = SWZ((uint32_t)(wm + mt * 16 + a_row) * 128u + (ks * 2 + a_chk) * 16u);
                ldsm_x4(a_h[mt], st + OFF_AH + off);
                ldsm_x4(a_l[mt], st + OFF_AL + off);
            }
            #pragma unroll
            for (int p = 0; p < 4; p++) {
                uint32_t off = SWZ((uint32_t)(brow0 + p * 16 + b_row) * 128u + (ks * 2 + b_chk) * 16u);
                uint32_t rh[4], rl[4];
                ldsm_x4(rh, st + OFF_BH + bsel + off);
                ldsm_x4(rl, st + OFF_BL + bsel + off);
                b_h[2*p][0]=rh[0]; b_h[2*p][1]=rh[1]; b_h[2*p+1][0]=rh[2]; b_h[2*p+1][1]=rh[3];
                b_l[2*p][0]=rl[0]; b_l[2*p][1]=rl[1]; b_l[2*p+1][0]=rl[2]; b_l[2*p+1][1]=rl[3];
            }
            #pragma unroll
            for (int mt = 0; mt < 4; mt++)
                #pragma unroll
                for (int nt = 0; nt < 8; nt++) {
                    mma_bf16(acc[mt][nt], a_h[mt], b_h[nt]);
                    mma_bf16(acc[mt][nt], a_h[mt], b_l[nt]);
                    mma_bf16(acc[mt][nt], a_l[mt], b_h[nt]);
                }
        }
        __syncthreads();
        if (tid == 0 && t + 2 < KBk) load_stage(t + 2);
    }

    #pragma unroll
    for (int mt = 0; mt < 4; mt++) {
        #pragma unroll
        for (int half = 0; half < 2; half++) {
            const int row = m0 + wm + mt * 16 + half * 8 + (lane >> 2);
            #pragma unroll
            for (int nt = 0; nt < 8; nt++) {
                const int col = n0 + wn + nt * 8 + (lane & 3) * 2;
                float v0 = acc[mt][nt][half * 2 + 0];
                float v1 = acc[mt][nt][half * 2 + 1];
                if (EPI == 0) {
                    *(float2*)&C[(size_t)row * N + col] = make_float2(v0, v1);
                } else if (EPI == 2) {
                    const float2 e2 = *(const float2*)&extra[(size_t)row * N + col];
                    *(float2*)&C[(size_t)row * N + col] = make_float2(v0 + e2.x, v1 + e2.y);
                } else {
                    float pf = extra[(size_t)row * NEXP + (col / INTER)];
                    float s0 = v0 / (1.f + __expf(-v0)) * pf;
                    float s1 = v1 / (1.f + __expf(-v1)) * pf;
                    uint32_t pl;
                    uint32_t ph = pack_hilo(s0, s1, pl);
                    uint32_t inner = (uint32_t)(row & 127) * 128u + (uint32_t)(col & 63) * 2u;
                    size_t off = (((size_t)(row >> 7) * CKB + (col >> 6)) << 14) + SWZ(inner);
                    *(uint32_t*)((char*)Ch + off) = ph;
                    *(uint32_t*)((char*)Cl + off) = pl;
                }
            }
        }
    }
}

// ---------------------------------------------------------------- tensor-core flash attention
// CTA = (head, 128-q tile). 8 warps, warp = 16 q rows. Split hi/lo 3-term QK and PV.
#define AT_SMEM (1024 + 192 * 1024)

__global__ __launch_bounds__(256, 1) void attn_tc(
    const __nv_bfloat16* __restrict__ QHg, const __nv_bfloat16* __restrict__ QLg,
    const __nv_bfloat16* __restrict__ KHg, const __nv_bfloat16* __restrict__ KLg,
    const __nv_bfloat16* __restrict__ VHg, const __nv_bfloat16* __restrict__ VLg,
    __nv_bfloat16* __restrict__ Ch, __nv_bfloat16* __restrict__ Cl)
{
    extern __shared__ char smem[];
    const uint32_t sbb = smem_u32(smem);
    const uint32_t tb = (sbb + 1023u) & ~1023u;
    const uint32_t QH = tb, QL = tb + 32768u, KH = tb + 65536u, KL = tb + 98304u;
    const uint32_t VH0 = tb + 131072u, VL0 = tb + 163840u;   // [2] stages: +16384 apart

    const int tid = threadIdx.x, wid = tid >> 5, lane = tid & 31;
    const int idx = (int)gridDim.x - 1 - (int)blockIdx.x;    // heavy first
    const int qt = idx >> 4, h = idx & 15;
    const int wq = wid * 16;
    const int r = lane >> 2, c2 = (lane & 3) * 2;

    if (tid == 0) {
        MBAR_INIT(sbb, 1); MBAR_INIT(sbb + 8, 1);
    }
    __syncthreads();
    if (tid == 0) {
        MBAR_EXPECT(sbb, 65536u);
        bulk_g2s(QH, (const char*)QHg + ((size_t)(h * 16 + qt) << 15), 32768u, sbb);
        bulk_g2s(QL, (const char*)QLg + ((size_t)(h * 16 + qt) << 15), 32768u, sbb);
        // first KV stage
        MBAR_EXPECT(sbb + 8, 98304u);
        bulk_g2s(KH,  (const char*)KHg + ((size_t)(h * 16 + 0) << 15), 32768u, sbb + 8);
        bulk_g2s(KL,  (const char*)KLg + ((size_t)(h * 16 + 0) << 15), 32768u, sbb + 8);
        bulk_g2s(VH0, (const char*)VHg + ((size_t)(h * 16 + 0) << 14), 16384u, sbb + 8);
        bulk_g2s(VL0, (const char*)VLg + ((size_t)(h * 16 + 0) << 14), 16384u, sbb + 8);
    }

    float sc[16][4];
    float o[8][4];
    #pragma unroll
    for (int i = 0; i < 8; i++)
        #pragma unroll
        for (int j = 0; j < 4; j++) o[i][j] = 0.f;
    float m0 = -1e30f, m1 = -1e30f, l0 = 0.f, l1 = 0.f;
    const float SCL = 0.08838834764831845f * 1.44269504088896f;  // 128^-0.5 * log2(e)

    const uint32_t a_row = lane & 15, a_chk = lane >> 4;
    const uint32_t b_row = ((lane >> 4) & 1) * 8 + (lane & 7);
    const uint32_t b_chk = (lane >> 3) & 1;

    for (int kt = 0; kt <= qt; kt++) {
        MBAR_WAIT(sbb + 8, kt & 1);
        if (kt == 0) MBAR_WAIT(sbb, 0);

        // ---- S = Q K^T (3-term)
        #pragma unroll
        for (int nt = 0; nt < 16; nt++)
            #pragma unroll
            for (int j = 0; j < 4; j++) sc[nt][j] = 0.f;

        #pragma unroll
        for (int kc = 0; kc < 8; kc++) {
            const uint32_t db = (kc >> 2) * 16384u;
            const uint32_t acol = ((uint32_t)(kc * 16) + a_chk * 8u) & 63u;
            uint32_t aoff = db + SWZ((uint32_t)(wq + a_row) * 128u + acol * 2u);
            uint32_t a_h[4], a_l[4];
            ldsm_x4(a_h, QH + aoff);
            ldsm_x4(a_l, QL + aoff);
            const uint32_t bcol = ((uint32_t)(kc * 16) + b_chk * 8u) & 63u;
            #pragma unroll
            for (int p = 0; p < 8; p++) {
                uint32_t boff = db + SWZ((uint32_t)(p * 16 + b_row) * 128u + bcol * 2u);
                uint32_t rh[4], rl[4];
                ldsm_x4(rh, KH + boff);
                ldsm_x4(rl, KL + boff);
                uint32_t bh0[2] = {rh[0], rh[1]}, bh1[2] = {rh[2], rh[3]};
                uint32_t bl0[2] = {rl[0], rl[1]}, bl1[2] = {rl[2], rl[3]};
                mma_bf16(sc[2*p],   a_h, bh0);
                mma_bf16(sc[2*p],   a_h, bl0);
                mma_bf16(sc[2*p],   a_l, bh0);
                mma_bf16(sc[2*p+1], a_h, bh1);
                mma_bf16(sc[2*p+1], a_h, bl1);
                mma_bf16(sc[2*p+1], a_l, bh1);
            }
        }
        __syncthreads();   // done reading K smem
        if (tid == 0 && kt < qt) {
            const int nt1 = kt + 1;
            const uint32_t vb = ((uint32_t)(nt1 & 1)) * 16384u;
            MBAR_EXPECT(sbb + 8, 98304u);
            bulk_g2s(KH,       (const char*)KHg + ((size_t)(h * 16 + nt1) << 15), 32768u, sbb + 8);
            bulk_g2s(KL,       (const char*)KLg + ((size_t)(h * 16 + nt1) << 15), 32768u, sbb + 8);
            bulk_g2s(VH0 + vb, (const char*)VHg + ((size_t)(h * 16 + nt1) << 14), 16384u, sbb + 8);
            bulk_g2s(VL0 + vb, (const char*)VLg + ((size_t)(h * 16 + nt1) << 14), 16384u, sbb + 8);
        }

        // ---- online softmax (exp2 domain)
        const bool diag = (kt == qt);
        float nm0 = m0, nm1 = m1;
        #pragma unroll
        for (int nt = 0; nt < 16; nt++) {
            #pragma unroll
            for (int j = 0; j < 4; j++) {
                float v = sc[nt][j] * SCL;
                if (diag) {
                    int col = nt * 8 + c2 + (j & 1);
                    int rowl = wq + r + (j >> 1) * 8;
                    if (col > rowl) v = -1e30f;
                }
                sc[nt][j] = v;
            }
            nm0 = fmaxf(nm0, fmaxf(sc[nt][0], sc[nt][1]));
            nm1 = fmaxf(nm1, fmaxf(sc[nt][2], sc[nt][3]));
        }
        #pragma unroll
        for (int off = 1; off <= 2; off <<= 1) {
            nm0 = fmaxf(nm0, __shfl_xor_sync(0xffffffffu, nm0, off));
            nm1 = fmaxf(nm1, __shfl_xor_sync(0xffffffffu, nm1, off));
        }
        float rs0 = 0.f, rs1 = 0.f;
        #pragma unroll
        for (int nt = 0; nt < 16; nt++) {
            sc[nt][0] = exp2f(sc[nt][0] - nm0);
            sc[nt][1] = exp2f(sc[nt][1] - nm0);
            sc[nt][2] = exp2f(sc[nt][2] - nm1);
            sc[nt][3] = exp2f(sc[nt][3] - nm1);
            rs0 += sc[nt][0] + sc[nt][1];
            rs1 += sc[nt][2] + sc[nt][3];
        }
        #pragma unroll
        for (int off = 1; off <= 2; off <<= 1) {
            rs0 += __shfl_xor_sync(0xffffffffu, rs0, off);
            rs1 += __shfl_xor_sync(0xffffffffu, rs1, off);
        }
        float cr0 = exp2f(m0 - nm0), cr1 = exp2f(m1 - nm1);
        l0 = l0 * cr0 + rs0; l1 = l1 * cr1 + rs1;
        m0 = nm0; m1 = nm1;
        #pragma unroll
        for (int i = 0; i < 8; i++) {
            o[i][0] *= cr0; o[i][1] *= cr0;
            o[i][2] *= cr1; o[i][3] *= cr1;
        }

        // ---- O += P V  (3-term; A from registers)
        const uint32_t vbase = ((uint32_t)(kt & 1)) * 16384u;
        #pragma unroll
        for (int kc = 0; kc < 8; kc++) {
            uint32_t a_h[4], a_l[4];
            a_h[0] = pack_hilo(sc[2*kc][0],   sc[2*kc][1],   a_l[0]);
            a_h[1] = pack_hilo(sc[2*kc][2],   sc[2*kc][3],   a_l[1]);
            a_h[2] = pack_hilo(sc[2*kc+1][0], sc[2*kc+1][1], a_l[2]);
            a_h[3] = pack_hilo(sc[2*kc+1][2], sc[2*kc+1][3], a_l[3]);
            const uint32_t scol = (uint32_t)(kc * 16) + b_chk * 8u;
            const uint32_t sub = (scol >> 6) * 8192u;
            #pragma unroll
            for (int p = 0; p < 4; p++) {
                uint32_t boff = sub + SWZ((uint32_t)(p * 16 + b_row) * 128u + (scol & 63u) * 2u);
                uint32_t rh[4], rl[4];
                ldsm_x4(rh, VH0 + vbase + boff);
                ldsm_x4(rl, VL0 + vbase + boff);
                uint32_t bh0[2] = {rh[0], rh[1]}, bh1[2] = {rh[2], rh[3]};
                uint32_t bl0[2] = {rl[0], rl[1]}, bl1[2] = {rl[2], rl[3]};
                mma_bf16(o[2*p],   a_h, bh0);
                mma_bf16(o[2*p],   a_h, bl0);
                mma_bf16(o[2*p],   a_l, bh0);
                mma_bf16(o[2*p+1], a_h, bh1);
                mma_bf16(o[2*p+1], a_h, bl1);
                mma_bf16(o[2*p+1], a_l, bh1);
            }
        }
    }

    // ---- normalize + write ctx (blocked hi/lo, KB_CTX)
    const float i0 = 1.f / l0, i1 = 1.f / l1;
    #pragma unroll
    for (int nt = 0; nt < 8; nt++) {
        const int col = h * DV + nt * 8 + c2;
        #pragma unroll
        for (int half = 0; half < 2; half++) {
            const int row = qt * 128 + wq + r + half * 8;
            float inv = half ? i1 : i0;
            float v0 = o[nt][half * 2 + 0] * inv;
            float v1 = o[nt][half * 2 + 1] * inv;
            uint32_t pl;
            uint32_t ph = pack_hilo(v0, v1, pl);
            uint32_t inner = (uint32_t)(row & 127) * 128u + (uint32_t)(col & 63) * 2u;
            size_t off = (((size_t)(row >> 7) * KB_CTX + (col >> 6)) << 14) + SWZ(inner);
            *(uint32_t*)((char*)Ch + off) = ph;
            *(uint32_t*)((char*)Cl + off) = pl;
        }
    }
}

// ---------------------------------------------------------------- launch
extern "C" void kernel_launch(void* const* d_in, const int* in_sizes, int n_in,
                              void* d_out, int out_size)
{
    const int*   positions = (const int*)  d_in[0];
    const float* hidden    = (const float*)d_in[1];
    const float* in_ln     = (const float*)d_in[2];
    const float* qw        = (const float*)d_in[3];
    const float* kva_w     = (const float*)d_in[4];
    const float* kvaln     = (const float*)d_in[5];
    const float* kvb_w     = (const float*)d_in[6];
    const float* ow        = (const float*)d_in[7];
    const float* postln    = (const float*)d_in[8];
    const float* gatew     = (const float*)d_in[9];
    const float* fc1w      = (const float*)d_in[10];
    const float* fc2w      = (const float*)d_in[11];
    float* out = (float*)d_out;

    float *sa, *qb, *ckv, *kvn, *kvv, *kpe, *x2, *mlp, *pr;
    cudaGetSymbolAddress((void**)&sa,  g_sa);
    cudaGetSymbolAddress((void**)&qb,  g_q);
    cudaGetSymbolAddress((void**)&ckv, g_ckv);
    cudaGetSymbolAddress((void**)&kvn, g_kvn);
    cudaGetSymbolAddress((void**)&kvv, g_kv);
    cudaGetSymbolAddress((void**)&kpe, g_kpe);
    cudaGetSymbolAddress((void**)&x2,  g_x2);
    cudaGetSymbolAddress((void**)&mlp, g_mlp);
    cudaGetSymbolAddress((void**)&pr,  g_pr);

    __nv_bfloat16 *sah,*sal,*kvnh,*kvnl,*mlph,*mlpl,*ctxh,*ctxl,*hbh,*hbl;
    __nv_bfloat16 *qwh,*qwl,*kvah,*kval,*kbwh,*kbwl,*owh,*owl,*f1h,*f1l,*f2h,*f2l;
    __nv_bfloat16 *qbh,*qbl,*kbh,*kbl,*vth,*vtl;
    cudaGetSymbolAddress((void**)&sah,  g_sa_h);  cudaGetSymbolAddress((void**)&sal,  g_sa_l);
    cudaGetSymbolAddress((void**)&kvnh, g_kvn_h); cudaGetSymbolAddress((void**)&kvnl, g_kvn_l);
    cudaGetSymbolAddress((void**)&mlph, g_mlp_h); cudaGetSymbolAddress((void**)&mlpl, g_mlp_l);
    cudaGetSymbolAddress((void**)&ctxh, g_ctx_h); cudaGetSymbolAddress((void**)&ctxl, g_ctx_l);
    cudaGetSymbolAddress((void**)&hbh,  g_hb_h);  cudaGetSymbolAddress((void**)&hbl,  g_hb_l);
    cudaGetSymbolAddress((void**)&qwh,  g_qw_h);  cudaGetSymbolAddress((void**)&qwl,  g_qw_l);
    cudaGetSymbolAddress((void**)&kvah, g_kva_h); cudaGetSymbolAddress((void**)&kval, g_kva_l);
    cudaGetSymbolAddress((void**)&kbwh, g_kbw_h); cudaGetSymbolAddress((void**)&kbwl, g_kbw_l);
    cudaGetSymbolAddress((void**)&owh,  g_ow_h);  cudaGetSymbolAddress((void**)&owl,  g_ow_l);
    cudaGetSymbolAddress((void**)&f1h,  g_f1_h);  cudaGetSymbolAddress((void**)&f1l,  g_f1_l);
    cudaGetSymbolAddress((void**)&f2h,  g_f2_h);  cudaGetSymbolAddress((void**)&f2l,  g_f2_l);
    cudaGetSymbolAddress((void**)&qbh,  g_qb_h);  cudaGetSymbolAddress((void**)&qbl,  g_qb_l);
    cudaGetSymbolAddress((void**)&kbh,  g_kb_h);  cudaGetSymbolAddress((void**)&kbl,  g_kb_l);
    cudaGetSymbolAddress((void**)&vth,  g_vt_h);  cudaGetSymbolAddress((void**)&vtl,  g_vt_l);

    cudaFuncSetAttribute(bgemm<0>, cudaFuncAttributeMaxDynamicSharedMemorySize, BG_SMEM);
    cudaFuncSetAttribute(bgemm<1>, cudaFuncAttributeMaxDynamicSharedMemorySize, BG_SMEM);
    cudaFuncSetAttribute(bgemm<2>, cudaFuncAttributeMaxDynamicSharedMemorySize, BG_SMEM);
    cudaFuncSetAttribute(attn_tc,  cudaFuncAttributeMaxDynamicSharedMemorySize, AT_SMEM);

    // weight converts -> blocked hi/lo
    cvt_blk_kernel<<<2048, 256>>>(qw,    qwh,  qwl,  H_DIM, H_DIM, H_DIM);
    cvt_blk_kernel<<<512,  256>>>(kva_w, kvah, kval, CKV_P, KVR + 64, H_DIM);
    cvt_blk_kernel<<<512,  256>>>(kvb_w, kbwh, kbwl, H_DIM, H_DIM, KVR);
    cvt_blk_kernel<<<1024, 256>>>(ow,    owh,  owl,  H_DIM, H_DIM, NHEAD * DV);
    cvt_blk_kernel<<<4096, 256>>>(fc1w,  f1h,  f1l,  NFC1, NFC1, H_DIM);
    cvt_fc2_blk_kernel<<<4096, 256>>>(fc2w, f2h, f2l);

    // 1. input RMSNorm
    rmsnorm_kernel<<<S_LEN, 256>>>(hidden, in_ln, sa, sah, sal, H_DIM, H_DIM, KB_H);
    // 2. q projection
    bgemm<0><<<dim3(8, 16), 256, BG_SMEM>>>(sah, sal, qwh, qwl, H_DIM, KB_H,
        qb, nullptr, nullptr, nullptr, 0);
    // 3. kv_a projection (padded N=512)
    bgemm<0><<<dim3(2, 16), 256, BG_SMEM>>>(sah, sal, kvah, kval, CKV_P, KB_H,
        ckv, nullptr, nullptr, nullptr, 0);
    // 4. kv RMSNorm
    rmsnorm_kernel<<<S_LEN, 256>>>(ckv, kvaln, kvn, kvnh, kvnl, KVR, CKV_P, KB_KVR);
    // 5. kv_b projection
    bgemm<0><<<dim3(8, 16), 256, BG_SMEM>>>(kvnh, kvnl, kbwh, kbwl, H_DIM, KB_KVR,
        kvv, nullptr, nullptr, nullptr, 0);
    // 6. RoPE
    rope_kernel<<<S_LEN, 256>>>(positions, qb, ckv, kpe);
    // 7. attention operand converts
    qk_cvt_kernel<<<S_LEN, 256>>>(qb, kvv, kpe, qbh, qbl, kbh, kbl);
    vt_cvt_kernel<<<dim3(S_LEN / 128, NHEAD), 256>>>(kvv, vth, vtl);
    // 8. tensor-core attention
    attn_tc<<<256, 256, AT_SMEM>>>(qbh, qbl, kbh, kbl, vth, vtl, ctxh, ctxl);
    // 9. o projection + residual
    bgemm<2><<<dim3(8, 16), 256, BG_SMEM>>>(ctxh, ctxl, owh, owl, H_DIM, KB_CTX,
        x2, hidden, nullptr, nullptr, 0);
    // 10. post RMSNorm
    rmsnorm_kernel<<<S_LEN, 256>>>(x2, postln, mlp, mlph, mlpl, H_DIM, H_DIM, KB_H);
    // 11. gate softmax
    gate_kernel<<<S_LEN, 256>>>(mlp, gatew, pr);
    // 12. fc1 + SiLU*probs
    bgemm<1><<<dim3(NFC1 / 256, 16), 256, BG_SMEM>>>(mlph, mlpl, f1h, f1l, NFC1, KB_H,
        nullptr, pr, hbh, hbl, KB_FC2);
    // 13. fc2 + residual -> out
    bgemm<2><<<dim3(8, 16), 256, BG_SMEM>>>(hbh, hbl, f2h, f2l, H_DIM, KB_FC2,
        out, x2, nullptr, nullptr, 0);
}